// round 2
// baseline (speedup 1.0000x reference)
#include <cuda_runtime.h>
#include <cstdint>
#include <math.h>

// Problem constants
#define B_DIM   1024
#define S_IN    4096
#define S_OUTD  4096
#define KNOT    8
#define HID     512
#define NCOL    (S_OUTD * 3 * KNOT)    // 98304
#define NELEM   ((size_t)B_DIM * S_IN) // 4194304
#define TWO_PI_F 6.28318530717958647692f
#define TWO_PI_D 6.283185307179586476925286766559
#define EPS_D    1e-6

// ---------------- device scratch (static, no allocation) ----------------
static __device__ double g_sum;
static __device__ double g_sumsq;
static __device__ float  g_mean;
static __device__ float  g_std;
static __device__ float  g_XN[NELEM];                  // normalized input, 16 MB
static __device__ float  g_H[B_DIM * HID];             // tanh(xn@w1+b1), 2 MB
static __device__ float  g_lg[(size_t)B_DIM * S_OUTD]; // log(grad), 16 MB

// ---------------- kernel: zero the scratch accumulators ----------------
__global__ void k_zero() {
    if (threadIdx.x == 0) { g_sum = 0.0; g_sumsq = 0.0; }
}

// ---------------- kernel: mean / sumsq of x_passive (double accum) ------
__global__ void k_stats(const float* __restrict__ xp) {
    double s = 0.0, s2 = 0.0;
    for (size_t i = (size_t)blockIdx.x * blockDim.x + threadIdx.x; i < NELEM;
         i += (size_t)gridDim.x * blockDim.x) {
        float v = xp[i];
        s  += (double)v;
        s2 += (double)v * (double)v;
    }
    __shared__ double sh[256];
    __shared__ double sh2[256];
    sh[threadIdx.x] = s; sh2[threadIdx.x] = s2;
    __syncthreads();
    for (int o = 128; o > 0; o >>= 1) {
        if (threadIdx.x < o) {
            sh[threadIdx.x]  += sh[threadIdx.x + o];
            sh2[threadIdx.x] += sh2[threadIdx.x + o];
        }
        __syncthreads();
    }
    if (threadIdx.x == 0) {
        atomicAdd(&g_sum,  sh[0]);
        atomicAdd(&g_sumsq, sh2[0]);
    }
}

// ---------------- kernel: finalize mean / std --------------------------
__global__ void k_finalize() {
    if (threadIdx.x == 0) {
        double n = (double)NELEM;
        double mean = g_sum / n;
        double var  = (g_sumsq - g_sum * g_sum / n) / (n - 1.0);
        g_mean = (float)mean;
        g_std  = (float)sqrt(var);
    }
}

// ---------------- kernel: xn = (x - mean) / std  (fp32, like reference) -
__global__ void k_xn(const float* __restrict__ xp) {
    float mean = g_mean, sd = g_std;
    for (size_t i = (size_t)blockIdx.x * blockDim.x + threadIdx.x; i < NELEM;
         i += (size_t)gridDim.x * blockDim.x) {
        g_XN[i] = (xp[i] - mean) / sd;
    }
}

// ---------------- kernel: GEMM1  H = tanh(xn @ w1 + b1) -----------------
// Tile 64x64, 256 thr, 4x4 microtile. fp32 inner accum, double flush
// every 64 k-steps (chunked compensation: error ~3e-7 instead of ~4e-6).
__global__ __launch_bounds__(256, 2)
void k_gemm1(const float* __restrict__ w1, const float* __restrict__ b1) {
    __shared__ float As[32 * 68];                    // [k][m], pad 68
    __shared__ __align__(16) float Bs[32 * 64];      // [k][n]
    const int tid = threadIdx.x;
    const int m0 = blockIdx.x * 64;
    const int n0 = blockIdx.y * 64;
    const int tx = tid & 15;
    const int ty = tid >> 4;

    float  acc[4][4];
    double accd[4][4];
#pragma unroll
    for (int i = 0; i < 4; i++)
#pragma unroll
        for (int j = 0; j < 4; j++) { acc[i][j] = 0.f; accd[i][j] = 0.0; }

    for (int c = 0; c < S_IN / 32; c++) {
        int k0 = c * 32;
        __syncthreads();
#pragma unroll
        for (int p = 0; p < 2; p++) {
            int idx = tid + p * 256;
            int m  = idx >> 3;
            int kq = idx & 7;
            float4 a = *(const float4*)(g_XN + (size_t)(m0 + m) * S_IN + k0 + kq * 4);
            As[(kq * 4 + 0) * 68 + m] = a.x;
            As[(kq * 4 + 1) * 68 + m] = a.y;
            As[(kq * 4 + 2) * 68 + m] = a.z;
            As[(kq * 4 + 3) * 68 + m] = a.w;
            int kb = idx >> 4;
            int nq = idx & 15;
            *(float4*)(Bs + kb * 64 + nq * 4) =
                *(const float4*)(w1 + (size_t)(k0 + kb) * HID + n0 + nq * 4);
        }
        __syncthreads();
#pragma unroll
        for (int k = 0; k < 32; k++) {
            float4 a = *(const float4*)(As + k * 68 + ty * 4);
            float4 b = *(const float4*)(Bs + k * 64 + tx * 4);
            float av[4] = {a.x, a.y, a.z, a.w};
            float bv[4] = {b.x, b.y, b.z, b.w};
#pragma unroll
            for (int i = 0; i < 4; i++)
#pragma unroll
                for (int j = 0; j < 4; j++) acc[i][j] += av[i] * bv[j];
        }
        if ((c & 1) == 1) {   // flush every 64 k
#pragma unroll
            for (int i = 0; i < 4; i++)
#pragma unroll
                for (int j = 0; j < 4; j++) {
                    accd[i][j] += (double)acc[i][j];
                    acc[i][j] = 0.f;
                }
        }
    }

#pragma unroll
    for (int i = 0; i < 4; i++) {
        int row = m0 + ty * 4 + i;
#pragma unroll
        for (int j = 0; j < 4; j++) {
            int col = n0 + tx * 4 + j;
            float val = (float)accd[i][j] + b1[col];
            g_H[(size_t)row * HID + col] = tanhf(val);
        }
    }
}

// ---------------- kernel: GEMM2 + fused spline epilogue -----------------
// M=1024, N=98304, K=512.  CTA tile: 64 (m) x 96 (n = 4 spline groups).
// Packed f32x2 FMA inner accum; flush to double every 128 k-steps.
// Spline epilogue computed in double (wrap-boundary accuracy).
#define FMA2(accv, av, bv) \
    asm("fma.rn.f32x2 %0, %1, %2, %0;" : "+l"(accv) : "l"(av), "l"(bv))

__global__ __launch_bounds__(256, 2)
void k_gemm2(const float* __restrict__ w2, const float* __restrict__ b2,
             const float* __restrict__ x_in, const float* __restrict__ ps,
             float* __restrict__ out_phi) {
    __shared__ float As[32 * 65];                 // [k][m], pad 65
    __shared__ __align__(16) float Bs[32 * 96];   // [k][n]
    const int tid = threadIdx.x;
    const int m0 = blockIdx.x * 64;               // m fastest -> w2 L2 reuse
    const int n0 = blockIdx.y * 96;
    const int ml = tid & 63;
    const int sl = tid >> 6;

    unsigned long long acc[12];
    double accd[24];
#pragma unroll
    for (int j = 0; j < 12; j++) acc[j] = 0ULL;
#pragma unroll
    for (int j = 0; j < 24; j++) accd[j] = 0.0;

    float4 ra[2];   // staged A loads (64*32/4/256)
    float4 rb[3];   // staged B loads (32*96/4/256)

    // prefetch chunk 0
#pragma unroll
    for (int p = 0; p < 2; p++) {
        int idx = tid + p * 256;
        ra[p] = *(const float4*)(g_H + (size_t)(m0 + (idx >> 3)) * HID + (idx & 7) * 4);
    }
#pragma unroll
    for (int p = 0; p < 3; p++) {
        int idx = tid + p * 256;
        int kk = idx / 24;
        int n4 = idx - kk * 24;
        rb[p] = *(const float4*)(w2 + (size_t)kk * NCOL + n0 + n4 * 4);
    }

    for (int c = 0; c < 16; c++) {
        __syncthreads();
#pragma unroll
        for (int p = 0; p < 2; p++) {
            int idx = tid + p * 256;
            int m  = idx >> 3;
            int kq = idx & 7;
            As[(kq * 4 + 0) * 65 + m] = ra[p].x;
            As[(kq * 4 + 1) * 65 + m] = ra[p].y;
            As[(kq * 4 + 2) * 65 + m] = ra[p].z;
            As[(kq * 4 + 3) * 65 + m] = ra[p].w;
        }
#pragma unroll
        for (int p = 0; p < 3; p++) {
            int idx = tid + p * 256;
            int kk = idx / 24;
            int n4 = idx - kk * 24;
            *(float4*)(Bs + kk * 96 + n4 * 4) = rb[p];
        }
        __syncthreads();
        if (c < 15) {
            int k0 = (c + 1) * 32;
#pragma unroll
            for (int p = 0; p < 2; p++) {
                int idx = tid + p * 256;
                ra[p] = *(const float4*)(g_H + (size_t)(m0 + (idx >> 3)) * HID +
                                         k0 + (idx & 7) * 4);
            }
#pragma unroll
            for (int p = 0; p < 3; p++) {
                int idx = tid + p * 256;
                int kk = idx / 24;
                int n4 = idx - kk * 24;
                rb[p] = *(const float4*)(w2 + (size_t)(k0 + kk) * NCOL + n0 + n4 * 4);
            }
        }
#pragma unroll
        for (int k = 0; k < 32; k++) {
            float a = As[k * 65 + ml];
            unsigned int au = __float_as_uint(a);
            unsigned long long a2;
            asm("mov.b64 %0, {%1, %1};" : "=l"(a2) : "r"(au));
            const ulonglong2* bp =
                reinterpret_cast<const ulonglong2*>(Bs + k * 96 + sl * 24);
            ulonglong2 q0 = bp[0], q1 = bp[1], q2 = bp[2];
            ulonglong2 q3 = bp[3], q4 = bp[4], q5 = bp[5];
            FMA2(acc[0],  a2, q0.x); FMA2(acc[1],  a2, q0.y);
            FMA2(acc[2],  a2, q1.x); FMA2(acc[3],  a2, q1.y);
            FMA2(acc[4],  a2, q2.x); FMA2(acc[5],  a2, q2.y);
            FMA2(acc[6],  a2, q3.x); FMA2(acc[7],  a2, q3.y);
            FMA2(acc[8],  a2, q4.x); FMA2(acc[9],  a2, q4.y);
            FMA2(acc[10], a2, q5.x); FMA2(acc[11], a2, q5.y);
        }
        if ((c & 3) == 3) {   // flush every 128 k
#pragma unroll
            for (int j = 0; j < 12; j++) {
                accd[2 * j]     += (double)__uint_as_float((unsigned int)(acc[j] & 0xffffffffu));
                accd[2 * j + 1] += (double)__uint_as_float((unsigned int)(acc[j] >> 32));
                acc[j] = 0ULL;
            }
        }
    }

    // ---- fused spline epilogue (double precision): one (b,s) per thread
    const int b  = m0 + ml;
    const int cb = n0 + sl * 24;      // = s * 24
    const int s  = cb / 24;

    float v[24];
#pragma unroll
    for (int cc = 0; cc < 24; cc++)
        v[cc] = tanhf((float)(accd[cc] + (double)b2[cb + cc]));

    float hm = v[0], wm = v[8];
#pragma unroll
    for (int i = 1; i < KNOT; i++) {
        hm = fmaxf(hm, v[i]);
        wm = fmaxf(wm, v[8 + i]);
    }
    float he[KNOT], we[KNOT];
    double hs = 0.0, ws = 0.0, d[KNOT];
#pragma unroll
    for (int i = 0; i < KNOT; i++) {
        he[i] = expf(v[i] - hm);      hs += (double)he[i];
        we[i] = expf(v[8 + i] - wm);  ws += (double)we[i];
        d[i] = (double)log1pf(expf(v[16 + i]));
    }
    double hscale = TWO_PI_D / hs;
    double wscale = TWO_PI_D / ws;
    double h[KNOT], w[KNOT];
#pragma unroll
    for (int i = 0; i < KNOT; i++) {
        h[i] = (double)he[i] * hscale;
        w[i] = (double)we[i] * wscale;
    }

    double x = (double)x_in[(size_t)b * S_OUTD + s];

    int kc = 0;
    double cw = 0.0;
#pragma unroll
    for (int i = 0; i < KNOT; i++) {
        cw += w[i];
        kc += (cw < x) ? 1 : 0;
    }
    int ki = kc < (KNOT - 1) ? kc : (KNOT - 1);

    double w_k = 0.0, h_k = 0.0, d_k = 0.0, x_km1 = 0.0, phi_km1 = 0.0;
    double pw = 0.0, ph = 0.0;
#pragma unroll
    for (int i = 0; i < KNOT; i++) {
        if (i == ki) {
            w_k = w[i]; h_k = h[i]; d_k = d[i];
            x_km1 = (i == 0) ? -EPS_D : pw;
            phi_km1 = ph;
        }
        pw += w[i];
        ph += h[i];
    }
    int kn = (ki + 1) & (KNOT - 1);
    double d_kp1 = 0.0;
#pragma unroll
    for (int i = 0; i < KNOT; i++) if (i == kn) d_kp1 = d[i];

    double s_k   = h_k / w_k;
    double alpha = (x - x_km1) / w_k;
    double a1m   = alpha * (1.0 - alpha);
    double denom = s_k + (d_kp1 + d_k - 2.0 * s_k) * a1m;
    double phi   = phi_km1 + h_k * (s_k * alpha * alpha + d_k * a1m) / denom;
    phi += (double)ps[0];
    phi = fmod(phi, TWO_PI_D);
    if (phi < 0.0) phi += TWO_PI_D;
    out_phi[(size_t)b * S_OUTD + s] = (float)phi;

    double om   = 1.0 - alpha;
    double grad = s_k * s_k *
                  (d_kp1 * alpha * alpha + 2.0 * s_k * a1m + d_k * om * om) /
                  (denom * denom);
    g_lg[(size_t)b * S_OUTD + s] = (float)log(grad);
}

// ---------------- kernel: deterministic log-density reduction ----------
__global__ void k_ldsum(const float* __restrict__ ld_in,
                        float* __restrict__ out_ld) {
    __shared__ double sh[256];
    int b = blockIdx.x;
    double sm = 0.0;
    for (int i = threadIdx.x; i < S_OUTD; i += 256)
        sm += (double)g_lg[(size_t)b * S_OUTD + i];
    sh[threadIdx.x] = sm;
    __syncthreads();
    for (int o = 128; o > 0; o >>= 1) {
        if (threadIdx.x < o) sh[threadIdx.x] += sh[threadIdx.x + o];
        __syncthreads();
    }
    if (threadIdx.x == 0) out_ld[b] = (float)((double)ld_in[b] - sh[0]);
}

// ---------------- launcher ----------------------------------------------
extern "C" void kernel_launch(void* const* d_in, const int* in_sizes, int n_in,
                              void* d_out, int out_size) {
    const float* x_in      = (const float*)d_in[0];
    const float* x_passive = (const float*)d_in[1];
    const float* ld_in     = (const float*)d_in[2];
    const float* w1        = (const float*)d_in[3];
    const float* b1        = (const float*)d_in[4];
    const float* w2        = (const float*)d_in[5];
    const float* b2        = (const float*)d_in[6];
    const float* ps        = (const float*)d_in[7];
    (void)in_sizes; (void)n_in; (void)out_size;

    float* out_phi = (float*)d_out;
    float* out_ld  = (float*)d_out + (size_t)B_DIM * S_OUTD;

    k_zero<<<1, 32>>>();
    k_stats<<<256, 256>>>(x_passive);
    k_finalize<<<1, 32>>>();
    k_xn<<<512, 256>>>(x_passive);
    k_gemm1<<<dim3(B_DIM / 64, HID / 64), 256>>>(w1, b1);
    k_gemm2<<<dim3(B_DIM / 64, NCOL / 96), 256>>>(w2, b2, x_in, ps, out_phi);
    k_ldsum<<<B_DIM, 256>>>(ld_in, out_ld);
}

// round 4
// speedup vs baseline: 1.1645x; 1.1645x over previous
#include <cuda_runtime.h>
#include <cuda_bf16.h>
#include <cstdint>
#include <math.h>

// Problem constants
#define B_DIM   1024
#define S_IN    4096
#define S_OUTD  4096
#define KNOT    8
#define HID     512
#define NCOL    (S_OUTD * 3 * KNOT)    // 98304
#define NELEM   ((size_t)B_DIM * S_IN) // 4194304
#define TWO_PI_D 6.283185307179586476925286766559
#define EPS_D    1e-6

// ---------------- device scratch (static, no allocation) ----------------
static __device__ double g_sum;
static __device__ double g_sumsq;
static __device__ float  g_mean;
static __device__ float  g_std;
static __device__ __align__(16) float g_XN[NELEM];                  // 16 MB
static __device__ __align__(16) float g_lg[(size_t)B_DIM * S_OUTD]; // 16 MB
// bf16 3-way splits of H (A operand) and W2^T (B operand, [n][k] K-major)
static __device__ __align__(16) __nv_bfloat16 g_Ah[B_DIM * HID];
static __device__ __align__(16) __nv_bfloat16 g_Am[B_DIM * HID];
static __device__ __align__(16) __nv_bfloat16 g_Al[B_DIM * HID];
static __device__ __align__(16) __nv_bfloat16 g_Bh[(size_t)NCOL * HID];
static __device__ __align__(16) __nv_bfloat16 g_Bm[(size_t)NCOL * HID];
static __device__ __align__(16) __nv_bfloat16 g_Bl[(size_t)NCOL * HID];

// ---------------- small kernels -----------------------------------------
__global__ void k_zero() {
    if (threadIdx.x == 0) { g_sum = 0.0; g_sumsq = 0.0; }
}

__global__ void k_stats(const float* __restrict__ xp) {
    double s = 0.0, s2 = 0.0;
    for (size_t i = (size_t)blockIdx.x * blockDim.x + threadIdx.x; i < NELEM;
         i += (size_t)gridDim.x * blockDim.x) {
        float v = xp[i];
        s  += (double)v;
        s2 += (double)v * (double)v;
    }
    __shared__ double sh[256];
    __shared__ double sh2[256];
    sh[threadIdx.x] = s; sh2[threadIdx.x] = s2;
    __syncthreads();
    for (int o = 128; o > 0; o >>= 1) {
        if (threadIdx.x < o) {
            sh[threadIdx.x]  += sh[threadIdx.x + o];
            sh2[threadIdx.x] += sh2[threadIdx.x + o];
        }
        __syncthreads();
    }
    if (threadIdx.x == 0) {
        atomicAdd(&g_sum,  sh[0]);
        atomicAdd(&g_sumsq, sh2[0]);
    }
}

__global__ void k_finalize() {
    if (threadIdx.x == 0) {
        double n = (double)NELEM;
        double mean = g_sum / n;
        double var  = (g_sumsq - g_sum * g_sum / n) / (n - 1.0);
        g_mean = (float)mean;
        g_std  = (float)sqrt(var);
    }
}

__global__ void k_xn(const float* __restrict__ xp) {
    float mean = g_mean, sd = g_std;
    for (size_t i = (size_t)blockIdx.x * blockDim.x + threadIdx.x; i < NELEM;
         i += (size_t)gridDim.x * blockDim.x) {
        g_XN[i] = (xp[i] - mean) / sd;
    }
}

// ---------------- kernel: transpose + 3-way bf16 split of w2 ------------
// w2 [512, 98304] fp32 -> g_B{h,m,l} [98304, 512] bf16 (K-major rows).
__global__ void k_wsplit(const float* __restrict__ w2) {
    __shared__ float t[32][33];
    int n0 = blockIdx.x * 32, k0 = blockIdx.y * 32;
    int tx = threadIdx.x & 31, ty = threadIdx.x >> 5;   // 32 x 8
#pragma unroll
    for (int i = 0; i < 4; i++)
        t[ty + i * 8][tx] = w2[(size_t)(k0 + ty + i * 8) * NCOL + n0 + tx];
    __syncthreads();
#pragma unroll
    for (int i = 0; i < 4; i++) {
        int n = n0 + ty + i * 8;
        int k = k0 + tx;
        float v = t[tx][ty + i * 8];
        __nv_bfloat16 h = __float2bfloat16(v);
        float r = v - __bfloat162float(h);
        __nv_bfloat16 m = __float2bfloat16(r);
        float r2 = r - __bfloat162float(m);
        size_t o = (size_t)n * HID + k;
        g_Bh[o] = h; g_Bm[o] = m; g_Bl[o] = __float2bfloat16(r2);
    }
}

// ---------------- kernel: GEMM1  H = tanh(xn @ w1 + b1), split to bf16 --
__global__ __launch_bounds__(256, 2)
void k_gemm1(const float* __restrict__ w1, const float* __restrict__ b1) {
    __shared__ float As[32 * 68];
    __shared__ __align__(16) float Bs[32 * 64];
    const int tid = threadIdx.x;
    const int m0 = blockIdx.x * 64;
    const int n0 = blockIdx.y * 64;
    const int tx = tid & 15;
    const int ty = tid >> 4;

    float  acc[4][4];
    double accd[4][4];
#pragma unroll
    for (int i = 0; i < 4; i++)
#pragma unroll
        for (int j = 0; j < 4; j++) { acc[i][j] = 0.f; accd[i][j] = 0.0; }

    for (int c = 0; c < S_IN / 32; c++) {
        int k0 = c * 32;
        __syncthreads();
#pragma unroll
        for (int p = 0; p < 2; p++) {
            int idx = tid + p * 256;
            int m  = idx >> 3;
            int kq = idx & 7;
            float4 a = *(const float4*)(g_XN + (size_t)(m0 + m) * S_IN + k0 + kq * 4);
            As[(kq * 4 + 0) * 68 + m] = a.x;
            As[(kq * 4 + 1) * 68 + m] = a.y;
            As[(kq * 4 + 2) * 68 + m] = a.z;
            As[(kq * 4 + 3) * 68 + m] = a.w;
            int kb = idx >> 4;
            int nq = idx & 15;
            *(float4*)(Bs + kb * 64 + nq * 4) =
                *(const float4*)(w1 + (size_t)(k0 + kb) * HID + n0 + nq * 4);
        }
        __syncthreads();
#pragma unroll
        for (int k = 0; k < 32; k++) {
            float4 a = *(const float4*)(As + k * 68 + ty * 4);
            float4 b = *(const float4*)(Bs + k * 64 + tx * 4);
            float av[4] = {a.x, a.y, a.z, a.w};
            float bv[4] = {b.x, b.y, b.z, b.w};
#pragma unroll
            for (int i = 0; i < 4; i++)
#pragma unroll
                for (int j = 0; j < 4; j++) acc[i][j] += av[i] * bv[j];
        }
        if ((c & 1) == 1) {
#pragma unroll
            for (int i = 0; i < 4; i++)
#pragma unroll
                for (int j = 0; j < 4; j++) {
                    accd[i][j] += (double)acc[i][j];
                    acc[i][j] = 0.f;
                }
        }
    }

#pragma unroll
    for (int i = 0; i < 4; i++) {
        int row = m0 + ty * 4 + i;
#pragma unroll
        for (int j = 0; j < 4; j++) {
            int col = n0 + tx * 4 + j;
            float t = tanhf((float)accd[i][j] + b1[col]);
            __nv_bfloat16 h = __float2bfloat16(t);
            float r = t - __bfloat162float(h);
            __nv_bfloat16 m = __float2bfloat16(r);
            float r2 = r - __bfloat162float(m);
            size_t o = (size_t)row * HID + col;
            g_Ah[o] = h; g_Am[o] = m; g_Al[o] = __float2bfloat16(r2);
        }
    }
}

// ---------------- mma.sync GEMM2 helpers ---------------------------------
#define SWZ128(x) ((x) ^ (((x) >> 3) & 0x70))

#define LDSM4(r, addr)                                                        \
    asm volatile("ldmatrix.sync.aligned.m8n8.x4.shared.b16 {%0,%1,%2,%3}, [%4];" \
                 : "=r"((r)[0]), "=r"((r)[1]), "=r"((r)[2]), "=r"((r)[3])     \
                 : "r"(addr))

#define MMA16816(d, a, b)                                                     \
    asm volatile("mma.sync.aligned.m16n8k16.row.col.f32.bf16.bf16.f32 "       \
                 "{%0,%1,%2,%3},{%4,%5,%6,%7},{%8,%9},{%0,%1,%2,%3};"         \
                 : "+f"((d)[0]), "+f"((d)[1]), "+f"((d)[2]), "+f"((d)[3])     \
                 : "r"((a)[0]), "r"((a)[1]), "r"((a)[2]), "r"((a)[3]),        \
                   "r"((b)[0]), "r"((b)[1]))

#define CP16(dst, src)                                                        \
    asm volatile("cp.async.cg.shared.global [%0], [%1], 16;" :: "r"(dst), "l"(src))

// SMEM layout (dynamic):
//   [0, 49152)        A buf0: 3 splits x 128 rows x 128B
//   [49152, 98304)    A buf1
//   [98304, 135168)   B buf0: 3 splits x 96 rows x 128B
//   [135168, 172032)  B buf1
// Epilogue aliases [0, 100352): main plane [128][98] f32 + corr plane.
#define A_BUFSZ 49152
#define A_PLANE 16384
#define B_OFF   98304
#define B_BUFSZ 36864
#define B_PLANE 12288
#define SMEMSZ  172032
#define EPIT    98      // epilogue plane pitch (floats)

// ---------------- kernel: GEMM2 (mma.sync) + fused spline epilogue ------
// CTA: M=128 x N=96 (4 spline groups), K=512 in 8 chunks of 64.
// 8 warps as 4(m) x 2(n): warp tile 32 x 48.
// 6 bf16-split products: hi*hi -> accm; {hi*mid, mid*hi, mid*mid,
// hi*lo, lo*hi} -> accc. Combined in double in the epilogue.
__global__ __launch_bounds__(256, 1)
void k_gemm2(const float* __restrict__ b2, const float* __restrict__ x_in,
             const float* __restrict__ ps, float* __restrict__ out_phi) {
    extern __shared__ char sm2[];
    const uint32_t sb = (uint32_t)__cvta_generic_to_shared(sm2);
    const int tid  = threadIdx.x;
    const int wid  = tid >> 5;
    const int lane = tid & 31;
    const int warp_m = wid & 3;        // m offset = warp_m*32
    const int warp_n = wid >> 2;       // n offset = warp_n*48
    const int m0 = blockIdx.x * 128;
    const int n0 = blockIdx.y * 96;

    float accm[12][4], accc[12][4];    // [mi*6+nj][4]
#pragma unroll
    for (int t = 0; t < 12; t++)
#pragma unroll
        for (int j = 0; j < 4; j++) { accm[t][j] = 0.f; accc[t][j] = 0.f; }

#define ISSUE(KC, BUF)                                                         \
    do {                                                                       \
        const int k0_ = (KC) * 64;                                             \
        _Pragma("unroll")                                                      \
        for (int p_ = 0; p_ < 12; p_++) {          /* A: 3072 16B chunks */    \
            int c_ = tid + p_ * 256;                                           \
            int s_ = c_ >> 10;                                                 \
            int rem_ = c_ & 1023;                                              \
            int r_ = rem_ >> 3, cell_ = rem_ & 7;                              \
            const __nv_bfloat16* src_ =                                        \
                (s_ == 0 ? g_Ah : (s_ == 1 ? g_Am : g_Al)) +                   \
                (size_t)(m0 + r_) * HID + k0_ + cell_ * 8;                     \
            uint32_t off_ = (uint32_t)(r_ * 128 + cell_ * 16);                 \
            CP16(sb + (BUF) * A_BUFSZ + s_ * A_PLANE + SWZ128(off_), src_);    \
        }                                                                      \
        _Pragma("unroll")                                                      \
        for (int p_ = 0; p_ < 9; p_++) {           /* B: 2304 16B chunks */    \
            int c_ = tid + p_ * 256;                                           \
            int s_ = c_ / 768;                                                 \
            int rem_ = c_ - s_ * 768;                                          \
            int r_ = rem_ >> 3, cell_ = rem_ & 7;                              \
            const __nv_bfloat16* src_ =                                        \
                (s_ == 0 ? g_Bh : (s_ == 1 ? g_Bm : g_Bl)) +                   \
                (size_t)(n0 + r_) * HID + k0_ + cell_ * 8;                     \
            uint32_t off_ = (uint32_t)(r_ * 128 + cell_ * 16);                 \
            CP16(sb + B_OFF + (BUF) * B_BUFSZ + s_ * B_PLANE + SWZ128(off_), src_); \
        }                                                                      \
        asm volatile("cp.async.commit_group;" ::: "memory");                   \
    } while (0)

    ISSUE(0, 0);

    for (int kc = 0; kc < 8; kc++) {
        if (kc < 7) {
            ISSUE(kc + 1, (kc + 1) & 1);
            asm volatile("cp.async.wait_group 1;" ::: "memory");
        } else {
            asm volatile("cp.async.wait_group 0;" ::: "memory");
        }
        __syncthreads();

        const uint32_t abase = sb + (kc & 1) * A_BUFSZ;
        const uint32_t bbase = sb + B_OFF + (kc & 1) * B_BUFSZ;

#pragma unroll
        for (int ks = 0; ks < 4; ks++) {
            uint32_t af[3][2][4];
#pragma unroll
            for (int s = 0; s < 3; s++)
#pragma unroll
                for (int mi = 0; mi < 2; mi++) {
                    int row = warp_m * 32 + mi * 16 + (lane & 15);
                    int off = row * 128 + ks * 32 + (lane >> 4) * 16;
                    LDSM4(af[s][mi], abase + s * A_PLANE + SWZ128(off));
                }
#pragma unroll
            for (int s = 0; s < 3; s++) {
                uint32_t bf[6][2];
#pragma unroll
                for (int j = 0; j < 3; j++) {
                    int row = warp_n * 48 + j * 16 + (lane & 7) + ((lane >> 4) & 1) * 8;
                    int off = row * 128 + ks * 32 + ((lane >> 3) & 1) * 16;
                    uint32_t q[4];
                    LDSM4(q, bbase + s * B_PLANE + SWZ128(off));
                    bf[2 * j][0] = q[0]; bf[2 * j][1] = q[1];
                    bf[2 * j + 1][0] = q[2]; bf[2 * j + 1][1] = q[3];
                }
                if (s == 0) {
#pragma unroll
                    for (int mi = 0; mi < 2; mi++)
#pragma unroll
                        for (int nj = 0; nj < 6; nj++)
                            MMA16816(accm[mi * 6 + nj], af[0][mi], bf[nj]);
#pragma unroll
                    for (int mi = 0; mi < 2; mi++)
#pragma unroll
                        for (int nj = 0; nj < 6; nj++)
                            MMA16816(accc[mi * 6 + nj], af[1][mi], bf[nj]);
#pragma unroll
                    for (int mi = 0; mi < 2; mi++)
#pragma unroll
                        for (int nj = 0; nj < 6; nj++)
                            MMA16816(accc[mi * 6 + nj], af[2][mi], bf[nj]);
                } else if (s == 1) {
#pragma unroll
                    for (int mi = 0; mi < 2; mi++)
#pragma unroll
                        for (int nj = 0; nj < 6; nj++)
                            MMA16816(accc[mi * 6 + nj], af[0][mi], bf[nj]);
#pragma unroll
                    for (int mi = 0; mi < 2; mi++)
#pragma unroll
                        for (int nj = 0; nj < 6; nj++)
                            MMA16816(accc[mi * 6 + nj], af[1][mi], bf[nj]);
                } else {
#pragma unroll
                    for (int mi = 0; mi < 2; mi++)
#pragma unroll
                        for (int nj = 0; nj < 6; nj++)
                            MMA16816(accc[mi * 6 + nj], af[0][mi], bf[nj]);
                }
            }
        }
        __syncthreads();   // protect buffers before next ISSUE overwrites
    }

    // ---- epilogue: exchange fragments through SMEM, then spline ----
    float* mp = (float*)sm2;               // main plane [128][EPIT]
    float* cp = (float*)sm2 + 128 * EPIT;  // corr plane
#pragma unroll
    for (int mi = 0; mi < 2; mi++)
#pragma unroll
        for (int nj = 0; nj < 6; nj++) {
            int t = mi * 6 + nj;
            int row = warp_m * 32 + mi * 16 + (lane >> 2);
            int col = warp_n * 48 + nj * 8 + (lane & 3) * 2;
            *(float2*)&mp[row * EPIT + col]       = make_float2(accm[t][0], accm[t][1]);
            *(float2*)&mp[(row + 8) * EPIT + col] = make_float2(accm[t][2], accm[t][3]);
            *(float2*)&cp[row * EPIT + col]       = make_float2(accc[t][0], accc[t][1]);
            *(float2*)&cp[(row + 8) * EPIT + col] = make_float2(accc[t][2], accc[t][3]);
        }
    __syncthreads();

#pragma unroll 1
    for (int it = 0; it < 2; it++) {
        int idx = tid + it * 256;          // 512 (b,s) pairs
        int m   = idx >> 2;                // 0..127
        int grp = idx & 3;                 // 0..3
        const int b = m0 + m;
        const int s_glob = blockIdx.y * 4 + grp;
        const int cb = s_glob * 24;

        float v[24];
#pragma unroll
        for (int cc = 0; cc < 24; cc++) {
            double mv = (double)mp[m * EPIT + grp * 24 + cc];
            double cv = (double)cp[m * EPIT + grp * 24 + cc];
            v[cc] = tanhf((float)(mv + cv + (double)b2[cb + cc]));
        }

        float hm = v[0], wm = v[8];
#pragma unroll
        for (int i = 1; i < KNOT; i++) {
            hm = fmaxf(hm, v[i]);
            wm = fmaxf(wm, v[8 + i]);
        }
        float he[KNOT], we[KNOT];
        double hs = 0.0, ws = 0.0, d[KNOT];
#pragma unroll
        for (int i = 0; i < KNOT; i++) {
            he[i] = expf(v[i] - hm);      hs += (double)he[i];
            we[i] = expf(v[8 + i] - wm);  ws += (double)we[i];
            d[i] = (double)log1pf(expf(v[16 + i]));
        }
        double hscale = TWO_PI_D / hs;
        double wscale = TWO_PI_D / ws;
        double h[KNOT], w[KNOT];
#pragma unroll
        for (int i = 0; i < KNOT; i++) {
            h[i] = (double)he[i] * hscale;
            w[i] = (double)we[i] * wscale;
        }

        double x = (double)x_in[(size_t)b * S_OUTD + s_glob];

        int kc2 = 0;
        double cw = 0.0;
#pragma unroll
        for (int i = 0; i < KNOT; i++) {
            cw += w[i];
            kc2 += (cw < x) ? 1 : 0;
        }
        int ki = kc2 < (KNOT - 1) ? kc2 : (KNOT - 1);

        double w_k = 0.0, h_k = 0.0, d_k = 0.0, x_km1 = 0.0, phi_km1 = 0.0;
        double pw = 0.0, ph = 0.0;
#pragma unroll
        for (int i = 0; i < KNOT; i++) {
            if (i == ki) {
                w_k = w[i]; h_k = h[i]; d_k = d[i];
                x_km1 = (i == 0) ? -EPS_D : pw;
                phi_km1 = ph;
            }
            pw += w[i];
            ph += h[i];
        }
        int kn = (ki + 1) & (KNOT - 1);
        double d_kp1 = 0.0;
#pragma unroll
        for (int i = 0; i < KNOT; i++) if (i == kn) d_kp1 = d[i];

        double s_k   = h_k / w_k;
        double alpha = (x - x_km1) / w_k;
        double a1m   = alpha * (1.0 - alpha);
        double denom = s_k + (d_kp1 + d_k - 2.0 * s_k) * a1m;
        double phi   = phi_km1 + h_k * (s_k * alpha * alpha + d_k * a1m) / denom;
        phi += (double)ps[0];
        phi = fmod(phi, TWO_PI_D);
        if (phi < 0.0) phi += TWO_PI_D;
        out_phi[(size_t)b * S_OUTD + s_glob] = (float)phi;

        double om   = 1.0 - alpha;
        double grad = s_k * s_k *
                      (d_kp1 * alpha * alpha + 2.0 * s_k * a1m + d_k * om * om) /
                      (denom * denom);
        g_lg[(size_t)b * S_OUTD + s_glob] = (float)log(grad);
    }
#undef ISSUE
}

// ---------------- kernel: deterministic log-density reduction ----------
__global__ void k_ldsum(const float* __restrict__ ld_in,
                        float* __restrict__ out_ld) {
    __shared__ double sh[256];
    int b = blockIdx.x;
    double sm = 0.0;
    for (int i = threadIdx.x; i < S_OUTD; i += 256)
        sm += (double)g_lg[(size_t)b * S_OUTD + i];
    sh[threadIdx.x] = sm;
    __syncthreads();
    for (int o = 128; o > 0; o >>= 1) {
        if (threadIdx.x < o) sh[threadIdx.x] += sh[threadIdx.x + o];
        __syncthreads();
    }
    if (threadIdx.x == 0) out_ld[b] = (float)((double)ld_in[b] - sh[0]);
}

// ---------------- launcher ----------------------------------------------
extern "C" void kernel_launch(void* const* d_in, const int* in_sizes, int n_in,
                              void* d_out, int out_size) {
    const float* x_in      = (const float*)d_in[0];
    const float* x_passive = (const float*)d_in[1];
    const float* ld_in     = (const float*)d_in[2];
    const float* w1        = (const float*)d_in[3];
    const float* b1        = (const float*)d_in[4];
    const float* w2        = (const float*)d_in[5];
    const float* b2        = (const float*)d_in[6];
    const float* ps        = (const float*)d_in[7];
    (void)in_sizes; (void)n_in; (void)out_size;

    float* out_phi = (float*)d_out;
    float* out_ld  = (float*)d_out + (size_t)B_DIM * S_OUTD;

    cudaFuncSetAttribute(k_gemm2, cudaFuncAttributeMaxDynamicSharedMemorySize,
                         SMEMSZ);

    k_zero<<<1, 32>>>();
    k_stats<<<256, 256>>>(x_passive);
    k_finalize<<<1, 32>>>();
    k_xn<<<512, 256>>>(x_passive);
    k_wsplit<<<dim3(NCOL / 32, HID / 32), 256>>>(w2);
    k_gemm1<<<dim3(B_DIM / 64, HID / 64), 256>>>(w1, b1);
    k_gemm2<<<dim3(B_DIM / 128, NCOL / 96), 256, SMEMSZ>>>(b2, x_in, ps, out_phi);
    k_ldsum<<<B_DIM, 256>>>(ld_in, out_ld);
}

// round 5
// speedup vs baseline: 1.3974x; 1.2000x over previous
#include <cuda_runtime.h>
#include <cuda_fp16.h>
#include <cstdint>
#include <math.h>

// Problem constants
#define B_DIM   1024
#define S_IN    4096
#define S_OUTD  4096
#define KNOT    8
#define HID     512
#define NCOL    (S_OUTD * 3 * KNOT)    // 98304
#define NELEM   ((size_t)B_DIM * S_IN) // 4194304
#define TWO_PI_D 6.283185307179586476925286766559
#define EPS_D    1e-6
#define LO_SCALE 2048.0f
#define LO_INV   (1.0 / 2048.0)

// ---------------- device scratch (static, no allocation) ----------------
static __device__ double g_sum;
static __device__ double g_sumsq;
static __device__ float  g_mean;
static __device__ float  g_std;
static __device__ __align__(16) float g_XN[NELEM];                  // 16 MB
static __device__ __align__(16) float g_lg[(size_t)B_DIM * S_OUTD]; // 16 MB
// fp16 2-way splits (lo pre-scaled by 2048) of H and W2^T ([n][k] K-major)
static __device__ __align__(16) __half g_Ah[B_DIM * HID];
static __device__ __align__(16) __half g_Al[B_DIM * HID];
static __device__ __align__(16) __half g_Bh[(size_t)NCOL * HID];
static __device__ __align__(16) __half g_Bl[(size_t)NCOL * HID];

// ---------------- small kernels -----------------------------------------
__global__ void k_zero() {
    if (threadIdx.x == 0) { g_sum = 0.0; g_sumsq = 0.0; }
}

__global__ void k_stats(const float* __restrict__ xp) {
    double s = 0.0, s2 = 0.0;
    for (size_t i = (size_t)blockIdx.x * blockDim.x + threadIdx.x; i < NELEM;
         i += (size_t)gridDim.x * blockDim.x) {
        float v = xp[i];
        s  += (double)v;
        s2 += (double)v * (double)v;
    }
    __shared__ double sh[256];
    __shared__ double sh2[256];
    sh[threadIdx.x] = s; sh2[threadIdx.x] = s2;
    __syncthreads();
    for (int o = 128; o > 0; o >>= 1) {
        if (threadIdx.x < o) {
            sh[threadIdx.x]  += sh[threadIdx.x + o];
            sh2[threadIdx.x] += sh2[threadIdx.x + o];
        }
        __syncthreads();
    }
    if (threadIdx.x == 0) {
        atomicAdd(&g_sum,  sh[0]);
        atomicAdd(&g_sumsq, sh2[0]);
    }
}

__global__ void k_finalize() {
    if (threadIdx.x == 0) {
        double n = (double)NELEM;
        double mean = g_sum / n;
        double var  = (g_sumsq - g_sum * g_sum / n) / (n - 1.0);
        g_mean = (float)mean;
        g_std  = (float)sqrt(var);
    }
}

__global__ void k_xn(const float* __restrict__ xp) {
    float mean = g_mean, sd = g_std;
    for (size_t i = (size_t)blockIdx.x * blockDim.x + threadIdx.x; i < NELEM;
         i += (size_t)gridDim.x * blockDim.x) {
        g_XN[i] = (xp[i] - mean) / sd;
    }
}

// ---------------- kernel: transpose + fp16 2-split of w2 ----------------
// w2 [512, 98304] fp32 -> g_B{h,l} [98304, 512] fp16 (K-major rows).
__global__ void k_wsplit(const float* __restrict__ w2) {
    __shared__ float t[32][33];
    int n0 = blockIdx.x * 32, k0 = blockIdx.y * 32;
    int tx = threadIdx.x & 31, ty = threadIdx.x >> 5;   // 32 x 8
#pragma unroll
    for (int i = 0; i < 4; i++)
        t[ty + i * 8][tx] = w2[(size_t)(k0 + ty + i * 8) * NCOL + n0 + tx];
    __syncthreads();
#pragma unroll
    for (int i = 0; i < 4; i++) {
        int n = n0 + ty + i * 8;
        int k = k0 + tx;
        float v = t[tx][ty + i * 8];
        __half h = __float2half_rn(v);
        float r = v - __half2float(h);
        size_t o = (size_t)n * HID + k;
        g_Bh[o] = h;
        g_Bl[o] = __float2half_rn(r * LO_SCALE);
    }
}

// ---------------- kernel: GEMM1  H = tanh(xn @ w1 + b1), fp16 split -----
__global__ __launch_bounds__(256, 2)
void k_gemm1(const float* __restrict__ w1, const float* __restrict__ b1) {
    __shared__ float As[32 * 68];
    __shared__ __align__(16) float Bs[32 * 64];
    const int tid = threadIdx.x;
    const int m0 = blockIdx.x * 64;
    const int n0 = blockIdx.y * 64;
    const int tx = tid & 15;
    const int ty = tid >> 4;

    float  acc[4][4];
    double accd[4][4];
#pragma unroll
    for (int i = 0; i < 4; i++)
#pragma unroll
        for (int j = 0; j < 4; j++) { acc[i][j] = 0.f; accd[i][j] = 0.0; }

    for (int c = 0; c < S_IN / 32; c++) {
        int k0 = c * 32;
        __syncthreads();
#pragma unroll
        for (int p = 0; p < 2; p++) {
            int idx = tid + p * 256;
            int m  = idx >> 3;
            int kq = idx & 7;
            float4 a = *(const float4*)(g_XN + (size_t)(m0 + m) * S_IN + k0 + kq * 4);
            As[(kq * 4 + 0) * 68 + m] = a.x;
            As[(kq * 4 + 1) * 68 + m] = a.y;
            As[(kq * 4 + 2) * 68 + m] = a.z;
            As[(kq * 4 + 3) * 68 + m] = a.w;
            int kb = idx >> 4;
            int nq = idx & 15;
            *(float4*)(Bs + kb * 64 + nq * 4) =
                *(const float4*)(w1 + (size_t)(k0 + kb) * HID + n0 + nq * 4);
        }
        __syncthreads();
#pragma unroll
        for (int k = 0; k < 32; k++) {
            float4 a = *(const float4*)(As + k * 68 + ty * 4);
            float4 b = *(const float4*)(Bs + k * 64 + tx * 4);
            float av[4] = {a.x, a.y, a.z, a.w};
            float bv[4] = {b.x, b.y, b.z, b.w};
#pragma unroll
            for (int i = 0; i < 4; i++)
#pragma unroll
                for (int j = 0; j < 4; j++) acc[i][j] += av[i] * bv[j];
        }
        if ((c & 1) == 1) {
#pragma unroll
            for (int i = 0; i < 4; i++)
#pragma unroll
                for (int j = 0; j < 4; j++) {
                    accd[i][j] += (double)acc[i][j];
                    acc[i][j] = 0.f;
                }
        }
    }

#pragma unroll
    for (int i = 0; i < 4; i++) {
        int row = m0 + ty * 4 + i;
#pragma unroll
        for (int j = 0; j < 4; j++) {
            int col = n0 + tx * 4 + j;
            float t = tanhf((float)accd[i][j] + b1[col]);
            __half h = __float2half_rn(t);
            float r = t - __half2float(h);
            size_t o = (size_t)row * HID + col;
            g_Ah[o] = h;
            g_Al[o] = __float2half_rn(r * LO_SCALE);
        }
    }
}

// ---------------- mma.sync GEMM2 helpers ---------------------------------
#define SWZ128(x) ((x) ^ (((x) >> 3) & 0x70))

#define LDSM4(r, addr)                                                        \
    asm volatile("ldmatrix.sync.aligned.m8n8.x4.shared.b16 {%0,%1,%2,%3}, [%4];" \
                 : "=r"((r)[0]), "=r"((r)[1]), "=r"((r)[2]), "=r"((r)[3])     \
                 : "r"(addr))

#define MMA16816(d, a, b)                                                     \
    asm volatile("mma.sync.aligned.m16n8k16.row.col.f32.f16.f16.f32 "         \
                 "{%0,%1,%2,%3},{%4,%5,%6,%7},{%8,%9},{%0,%1,%2,%3};"         \
                 : "+f"((d)[0]), "+f"((d)[1]), "+f"((d)[2]), "+f"((d)[3])     \
                 : "r"((a)[0]), "r"((a)[1]), "r"((a)[2]), "r"((a)[3]),        \
                   "r"((b)[0]), "r"((b)[1]))

#define CP16(dst, src)                                                        \
    asm volatile("cp.async.cg.shared.global [%0], [%1], 16;" :: "r"(dst), "l"(src))

// SMEM: 4 stages x 56KB. Stage: A hi/lo planes [0,32768), B planes [32768,57344).
#define STAGE   57344
#define A_PLANE 16384
#define B_SOFF  32768
#define B_PLANE 12288
#define SMEMSZ  (4 * STAGE)   // 229376
#define EPIT    98            // epilogue plane pitch (floats)

// ---------------- kernel: GEMM2 (mma.sync fp16-split) + spline ----------
// CTA: M=128 x N=96 (4 spline groups), K=512 in 8 chunks of 64.
// 8 warps as 4(m) x 2(n): warp tile 32 x 48.
// Products: Ah*Bh -> accm; Ah*Bl' + Al'*Bh -> accc (scale 2048, fixed in epi).
__global__ __launch_bounds__(256, 1)
void k_gemm2(const float* __restrict__ b2, const float* __restrict__ x_in,
             const float* __restrict__ ps, float* __restrict__ out_phi) {
    extern __shared__ char sm2[];
    const uint32_t sb = (uint32_t)__cvta_generic_to_shared(sm2);
    const int tid  = threadIdx.x;
    const int wid  = tid >> 5;
    const int lane = tid & 31;
    const int warp_m = wid & 3;
    const int warp_n = wid >> 2;
    const int m0 = blockIdx.x * 128;
    const int n0 = blockIdx.y * 96;

    float accm[12][4], accc[12][4];
#pragma unroll
    for (int t = 0; t < 12; t++)
#pragma unroll
        for (int j = 0; j < 4; j++) { accm[t][j] = 0.f; accc[t][j] = 0.f; }

#define ISSUE(KC)                                                              \
    do {                                                                       \
        const int k0_ = (KC) * 64;                                             \
        const uint32_t st_ = sb + ((KC) & 3) * STAGE;                          \
        _Pragma("unroll")                                                      \
        for (int p_ = 0; p_ < 8; p_++) {          /* A: 2048 16B chunks */     \
            int c_ = tid + p_ * 256;                                           \
            int s_ = c_ >> 10;                                                 \
            int rem_ = c_ & 1023;                                              \
            int r_ = rem_ >> 3, cell_ = rem_ & 7;                              \
            const __half* src_ = (s_ == 0 ? g_Ah : g_Al) +                     \
                                 (size_t)(m0 + r_) * HID + k0_ + cell_ * 8;    \
            uint32_t off_ = (uint32_t)(r_ * 128 + cell_ * 16);                 \
            CP16(st_ + s_ * A_PLANE + SWZ128(off_), src_);                     \
        }                                                                      \
        _Pragma("unroll")                                                      \
        for (int p_ = 0; p_ < 6; p_++) {          /* B: 1536 16B chunks */     \
            int c_ = tid + p_ * 256;                                           \
            int s_ = c_ / 768;                                                 \
            int rem_ = c_ - s_ * 768;                                          \
            int r_ = rem_ >> 3, cell_ = rem_ & 7;                              \
            const __half* src_ = (s_ == 0 ? g_Bh : g_Bl) +                     \
                                 (size_t)(n0 + r_) * HID + k0_ + cell_ * 8;    \
            uint32_t off_ = (uint32_t)(r_ * 128 + cell_ * 16);                 \
            CP16(st_ + B_SOFF + s_ * B_PLANE + SWZ128(off_), src_);            \
        }                                                                      \
        asm volatile("cp.async.commit_group;" ::: "memory");                   \
    } while (0)

    ISSUE(0); ISSUE(1); ISSUE(2);

    for (int kc = 0; kc < 8; kc++) {
        if (kc <= 5)      asm volatile("cp.async.wait_group 2;" ::: "memory");
        else if (kc == 6) asm volatile("cp.async.wait_group 1;" ::: "memory");
        else              asm volatile("cp.async.wait_group 0;" ::: "memory");
        __syncthreads();

        const uint32_t abase = sb + (kc & 3) * STAGE;
        const uint32_t bbase = abase + B_SOFF;

#pragma unroll
        for (int ks = 0; ks < 4; ks++) {
            uint32_t af[2][2][4];   // [split][mi]
#pragma unroll
            for (int s = 0; s < 2; s++)
#pragma unroll
                for (int mi = 0; mi < 2; mi++) {
                    int row = warp_m * 32 + mi * 16 + (lane & 15);
                    int off = row * 128 + ks * 32 + (lane >> 4) * 16;
                    LDSM4(af[s][mi], abase + s * A_PLANE + SWZ128(off));
                }
#pragma unroll
            for (int s = 0; s < 2; s++) {
                uint32_t bf[6][2];
#pragma unroll
                for (int j = 0; j < 3; j++) {
                    int row = warp_n * 48 + j * 16 + (lane & 7) + ((lane >> 4) & 1) * 8;
                    int off = row * 128 + ks * 32 + ((lane >> 3) & 1) * 16;
                    uint32_t q[4];
                    LDSM4(q, bbase + s * B_PLANE + SWZ128(off));
                    bf[2 * j][0] = q[0]; bf[2 * j][1] = q[1];
                    bf[2 * j + 1][0] = q[2]; bf[2 * j + 1][1] = q[3];
                }
                if (s == 0) {
                    // Ah*Bh -> accm ; Al'*Bh -> accc
#pragma unroll
                    for (int mi = 0; mi < 2; mi++)
#pragma unroll
                        for (int nj = 0; nj < 6; nj++)
                            MMA16816(accm[mi * 6 + nj], af[0][mi], bf[nj]);
#pragma unroll
                    for (int mi = 0; mi < 2; mi++)
#pragma unroll
                        for (int nj = 0; nj < 6; nj++)
                            MMA16816(accc[mi * 6 + nj], af[1][mi], bf[nj]);
                } else {
                    // Ah*Bl' -> accc
#pragma unroll
                    for (int mi = 0; mi < 2; mi++)
#pragma unroll
                        for (int nj = 0; nj < 6; nj++)
                            MMA16816(accc[mi * 6 + nj], af[0][mi], bf[nj]);
                }
            }
        }
        if (kc <= 4) ISSUE(kc + 3);
    }
    __syncthreads();

    // ---- epilogue: exchange fragments through SMEM, then spline ----
    float* mp = (float*)sm2;               // main plane [128][EPIT]
    float* cp = (float*)sm2 + 128 * EPIT;  // corr plane
#pragma unroll
    for (int mi = 0; mi < 2; mi++)
#pragma unroll
        for (int nj = 0; nj < 6; nj++) {
            int t = mi * 6 + nj;
            int row = warp_m * 32 + mi * 16 + (lane >> 2);
            int col = warp_n * 48 + nj * 8 + (lane & 3) * 2;
            *(float2*)&mp[row * EPIT + col]       = make_float2(accm[t][0], accm[t][1]);
            *(float2*)&mp[(row + 8) * EPIT + col] = make_float2(accm[t][2], accm[t][3]);
            *(float2*)&cp[row * EPIT + col]       = make_float2(accc[t][0], accc[t][1]);
            *(float2*)&cp[(row + 8) * EPIT + col] = make_float2(accc[t][2], accc[t][3]);
        }
    __syncthreads();

#pragma unroll 1
    for (int it = 0; it < 2; it++) {
        int idx = tid + it * 256;          // 512 (b,s) pairs
        int m   = idx >> 2;                // 0..127
        int grp = idx & 3;                 // 0..3
        const int b = m0 + m;
        const int s_glob = blockIdx.y * 4 + grp;
        const int cb = s_glob * 24;

        float v[24];
#pragma unroll
        for (int cc = 0; cc < 24; cc++) {
            double mv = (double)mp[m * EPIT + grp * 24 + cc];
            double cv = (double)cp[m * EPIT + grp * 24 + cc];
            v[cc] = tanhf((float)(mv + cv * LO_INV + (double)b2[cb + cc]));
        }

        float hm = v[0], wm = v[8];
#pragma unroll
        for (int i = 1; i < KNOT; i++) {
            hm = fmaxf(hm, v[i]);
            wm = fmaxf(wm, v[8 + i]);
        }
        float he[KNOT], we[KNOT];
        double hs = 0.0, ws = 0.0, d[KNOT];
#pragma unroll
        for (int i = 0; i < KNOT; i++) {
            he[i] = expf(v[i] - hm);      hs += (double)he[i];
            we[i] = expf(v[8 + i] - wm);  ws += (double)we[i];
            d[i] = (double)log1pf(expf(v[16 + i]));
        }
        double hscale = TWO_PI_D / hs;
        double wscale = TWO_PI_D / ws;
        double h[KNOT], w[KNOT];
#pragma unroll
        for (int i = 0; i < KNOT; i++) {
            h[i] = (double)he[i] * hscale;
            w[i] = (double)we[i] * wscale;
        }

        double x = (double)x_in[(size_t)b * S_OUTD + s_glob];

        int kc2 = 0;
        double cw = 0.0;
#pragma unroll
        for (int i = 0; i < KNOT; i++) {
            cw += w[i];
            kc2 += (cw < x) ? 1 : 0;
        }
        int ki = kc2 < (KNOT - 1) ? kc2 : (KNOT - 1);

        double w_k = 0.0, h_k = 0.0, d_k = 0.0, x_km1 = 0.0, phi_km1 = 0.0;
        double pw = 0.0, ph = 0.0;
#pragma unroll
        for (int i = 0; i < KNOT; i++) {
            if (i == ki) {
                w_k = w[i]; h_k = h[i]; d_k = d[i];
                x_km1 = (i == 0) ? -EPS_D : pw;
                phi_km1 = ph;
            }
            pw += w[i];
            ph += h[i];
        }
        int kn = (ki + 1) & (KNOT - 1);
        double d_kp1 = 0.0;
#pragma unroll
        for (int i = 0; i < KNOT; i++) if (i == kn) d_kp1 = d[i];

        double s_k   = h_k / w_k;
        double alpha = (x - x_km1) / w_k;
        double a1m   = alpha * (1.0 - alpha);
        double denom = s_k + (d_kp1 + d_k - 2.0 * s_k) * a1m;
        double phi   = phi_km1 + h_k * (s_k * alpha * alpha + d_k * a1m) / denom;
        phi += (double)ps[0];
        phi = fmod(phi, TWO_PI_D);
        if (phi < 0.0) phi += TWO_PI_D;
        out_phi[(size_t)b * S_OUTD + s_glob] = (float)phi;

        double om   = 1.0 - alpha;
        double grad = s_k * s_k *
                      (d_kp1 * alpha * alpha + 2.0 * s_k * a1m + d_k * om * om) /
                      (denom * denom);
        g_lg[(size_t)b * S_OUTD + s_glob] = (float)log(grad);
    }
#undef ISSUE
}

// ---------------- kernel: deterministic log-density reduction ----------
__global__ void k_ldsum(const float* __restrict__ ld_in,
                        float* __restrict__ out_ld) {
    __shared__ double sh[256];
    int b = blockIdx.x;
    double sm = 0.0;
    for (int i = threadIdx.x; i < S_OUTD; i += 256)
        sm += (double)g_lg[(size_t)b * S_OUTD + i];
    sh[threadIdx.x] = sm;
    __syncthreads();
    for (int o = 128; o > 0; o >>= 1) {
        if (threadIdx.x < o) sh[threadIdx.x] += sh[threadIdx.x + o];
        __syncthreads();
    }
    if (threadIdx.x == 0) out_ld[b] = (float)((double)ld_in[b] - sh[0]);
}

// ---------------- launcher ----------------------------------------------
extern "C" void kernel_launch(void* const* d_in, const int* in_sizes, int n_in,
                              void* d_out, int out_size) {
    const float* x_in      = (const float*)d_in[0];
    const float* x_passive = (const float*)d_in[1];
    const float* ld_in     = (const float*)d_in[2];
    const float* w1        = (const float*)d_in[3];
    const float* b1        = (const float*)d_in[4];
    const float* w2        = (const float*)d_in[5];
    const float* b2        = (const float*)d_in[6];
    const float* ps        = (const float*)d_in[7];
    (void)in_sizes; (void)n_in; (void)out_size;

    float* out_phi = (float*)d_out;
    float* out_ld  = (float*)d_out + (size_t)B_DIM * S_OUTD;

    cudaFuncSetAttribute(k_gemm2, cudaFuncAttributeMaxDynamicSharedMemorySize,
                         SMEMSZ);

    k_zero<<<1, 32>>>();
    k_stats<<<256, 256>>>(x_passive);
    k_finalize<<<1, 32>>>();
    k_xn<<<512, 256>>>(x_passive);
    k_wsplit<<<dim3(NCOL / 32, HID / 32), 256>>>(w2);
    k_gemm1<<<dim3(B_DIM / 64, HID / 64), 256>>>(w1, b1);
    k_gemm2<<<dim3(B_DIM / 128, NCOL / 96), 256, SMEMSZ>>>(b2, x_in, ps, out_phi);
    k_ldsum<<<B_DIM, 256>>>(ld_in, out_ld);
}

// round 6
// speedup vs baseline: 1.9717x; 1.4109x over previous
#include <cuda_runtime.h>
#include <cuda_fp16.h>
#include <cstdint>
#include <math.h>

// Problem constants
#define B_DIM   1024
#define S_IN    4096
#define S_OUTD  4096
#define KNOT    8
#define HID     512
#define NCOL    (S_OUTD * 3 * KNOT)    // 98304
#define NELEM   ((size_t)B_DIM * S_IN) // 4194304
#define TWO_PI_D 6.283185307179586476925286766559
#define EPS_D    1e-6
#define LO_SCALE 2048.0f
#define LO_INV   (1.0 / 2048.0)

// ---------------- device scratch (static, no allocation) ----------------
static __device__ double g_sum;
static __device__ double g_sumsq;
static __device__ float  g_mean;
static __device__ float  g_std;
static __device__ __align__(16) float g_XN[NELEM];                  // 16 MB
static __device__ __align__(16) float g_lg[(size_t)B_DIM * S_OUTD]; // 16 MB
// fp16 2-way splits (lo pre-scaled by 2048) of H and W2^T ([n][k] K-major)
static __device__ __align__(16) __half g_Ah[B_DIM * HID];
static __device__ __align__(16) __half g_Al[B_DIM * HID];
static __device__ __align__(16) __half g_Bh[(size_t)NCOL * HID];
static __device__ __align__(16) __half g_Bl[(size_t)NCOL * HID];

// ---------------- small kernels -----------------------------------------
__global__ void k_zero() {
    if (threadIdx.x == 0) { g_sum = 0.0; g_sumsq = 0.0; }
}

__global__ void k_stats(const float* __restrict__ xp) {
    double s = 0.0, s2 = 0.0;
    for (size_t i = (size_t)blockIdx.x * blockDim.x + threadIdx.x; i < NELEM;
         i += (size_t)gridDim.x * blockDim.x) {
        float v = xp[i];
        s  += (double)v;
        s2 += (double)v * (double)v;
    }
    __shared__ double sh[256];
    __shared__ double sh2[256];
    sh[threadIdx.x] = s; sh2[threadIdx.x] = s2;
    __syncthreads();
    for (int o = 128; o > 0; o >>= 1) {
        if (threadIdx.x < o) {
            sh[threadIdx.x]  += sh[threadIdx.x + o];
            sh2[threadIdx.x] += sh2[threadIdx.x + o];
        }
        __syncthreads();
    }
    if (threadIdx.x == 0) {
        atomicAdd(&g_sum,  sh[0]);
        atomicAdd(&g_sumsq, sh2[0]);
    }
}

__global__ void k_finalize() {
    if (threadIdx.x == 0) {
        double n = (double)NELEM;
        double mean = g_sum / n;
        double var  = (g_sumsq - g_sum * g_sum / n) / (n - 1.0);
        g_mean = (float)mean;
        g_std  = (float)sqrt(var);
    }
}

__global__ void k_xn(const float* __restrict__ xp) {
    float mean = g_mean, sd = g_std;
    float inv = 1.0f / sd;
    const float4* src = (const float4*)xp;
    float4* dst = (float4*)g_XN;
    for (size_t i = (size_t)blockIdx.x * blockDim.x + threadIdx.x;
         i < NELEM / 4; i += (size_t)gridDim.x * blockDim.x) {
        float4 v = src[i];
        v.x = (v.x - mean) * inv; v.y = (v.y - mean) * inv;
        v.z = (v.z - mean) * inv; v.w = (v.w - mean) * inv;
        dst[i] = v;
    }
}

// ---------------- kernel: transpose + fp16 2-split of w2 ----------------
// w2 [512, 98304] fp32 -> g_B{h,l} [98304, 512] fp16 (K-major rows).
// Tile: 32 n x 64 k; writes half2 along k (coalesced 128B).
__global__ void k_wsplit(const float* __restrict__ w2) {
    __shared__ float t[64][33];
    const int n0 = blockIdx.x * 32, k0 = blockIdx.y * 64;
    const int tid = threadIdx.x;
#pragma unroll
    for (int p = 0; p < 8; p++) {
        int idx = tid + p * 256;
        int kr = idx >> 5, nc = idx & 31;
        t[kr][nc] = w2[(size_t)(k0 + kr) * NCOL + n0 + nc];
    }
    __syncthreads();
#pragma unroll
    for (int p = 0; p < 4; p++) {
        int idx = tid + p * 256;
        int n = idx >> 5, kp = idx & 31;
        float v0 = t[2 * kp][n];
        float v1 = t[2 * kp + 1][n];
        __half h0 = __float2half_rn(v0);
        __half h1 = __float2half_rn(v1);
        __half l0 = __float2half_rn((v0 - __half2float(h0)) * LO_SCALE);
        __half l1 = __float2half_rn((v1 - __half2float(h1)) * LO_SCALE);
        size_t o = ((size_t)(n0 + n) * HID + k0 + 2 * kp) >> 1;
        ((__half2*)g_Bh)[o] = __halves2half2(h0, h1);
        ((__half2*)g_Bl)[o] = __halves2half2(l0, l1);
    }
}

// ---------------- kernel: GEMM1  H = tanh(xn @ w1 + b1), fp16 split -----
__global__ __launch_bounds__(256, 2)
void k_gemm1(const float* __restrict__ w1, const float* __restrict__ b1) {
    __shared__ float As[32 * 68];
    __shared__ __align__(16) float Bs[32 * 64];
    const int tid = threadIdx.x;
    const int m0 = blockIdx.x * 64;
    const int n0 = blockIdx.y * 64;
    const int tx = tid & 15;
    const int ty = tid >> 4;

    float  acc[4][4];
    double accd[4][4];
#pragma unroll
    for (int i = 0; i < 4; i++)
#pragma unroll
        for (int j = 0; j < 4; j++) { acc[i][j] = 0.f; accd[i][j] = 0.0; }

    for (int c = 0; c < S_IN / 32; c++) {
        int k0 = c * 32;
        __syncthreads();
#pragma unroll
        for (int p = 0; p < 2; p++) {
            int idx = tid + p * 256;
            int m  = idx >> 3;
            int kq = idx & 7;
            float4 a = *(const float4*)(g_XN + (size_t)(m0 + m) * S_IN + k0 + kq * 4);
            As[(kq * 4 + 0) * 68 + m] = a.x;
            As[(kq * 4 + 1) * 68 + m] = a.y;
            As[(kq * 4 + 2) * 68 + m] = a.z;
            As[(kq * 4 + 3) * 68 + m] = a.w;
            int kb = idx >> 4;
            int nq = idx & 15;
            *(float4*)(Bs + kb * 64 + nq * 4) =
                *(const float4*)(w1 + (size_t)(k0 + kb) * HID + n0 + nq * 4);
        }
        __syncthreads();
#pragma unroll
        for (int k = 0; k < 32; k++) {
            float4 a = *(const float4*)(As + k * 68 + ty * 4);
            float4 b = *(const float4*)(Bs + k * 64 + tx * 4);
            float av[4] = {a.x, a.y, a.z, a.w};
            float bv[4] = {b.x, b.y, b.z, b.w};
#pragma unroll
            for (int i = 0; i < 4; i++)
#pragma unroll
                for (int j = 0; j < 4; j++) acc[i][j] += av[i] * bv[j];
        }
        if ((c & 1) == 1) {
#pragma unroll
            for (int i = 0; i < 4; i++)
#pragma unroll
                for (int j = 0; j < 4; j++) {
                    accd[i][j] += (double)acc[i][j];
                    acc[i][j] = 0.f;
                }
        }
    }

#pragma unroll
    for (int i = 0; i < 4; i++) {
        int row = m0 + ty * 4 + i;
#pragma unroll
        for (int j = 0; j < 4; j++) {
            int col = n0 + tx * 4 + j;
            float t = tanhf((float)accd[i][j] + b1[col]);
            __half h = __float2half_rn(t);
            float r = t - __half2float(h);
            size_t o = (size_t)row * HID + col;
            g_Ah[o] = h;
            g_Al[o] = __float2half_rn(r * LO_SCALE);
        }
    }
}

// ---------------- mma.sync GEMM2 helpers ---------------------------------
#define SWZ128(x) ((x) ^ (((x) >> 3) & 0x70))

#define LDSM4(r, addr)                                                        \
    asm volatile("ldmatrix.sync.aligned.m8n8.x4.shared.b16 {%0,%1,%2,%3}, [%4];" \
                 : "=r"((r)[0]), "=r"((r)[1]), "=r"((r)[2]), "=r"((r)[3])     \
                 : "r"(addr))

#define MMA16816(d, a, b)                                                     \
    asm volatile("mma.sync.aligned.m16n8k16.row.col.f32.f16.f16.f32 "         \
                 "{%0,%1,%2,%3},{%4,%5,%6,%7},{%8,%9},{%0,%1,%2,%3};"         \
                 : "+f"((d)[0]), "+f"((d)[1]), "+f"((d)[2]), "+f"((d)[3])     \
                 : "r"((a)[0]), "r"((a)[1]), "r"((a)[2]), "r"((a)[3]),        \
                   "r"((b)[0]), "r"((b)[1]))

#define CP16(dst, src)                                                        \
    asm volatile("cp.async.cg.shared.global [%0], [%1], 16;" :: "r"(dst), "l"(src))

// SMEM: 4 stages x 28KB (K-chunk 32). Stage rows are 128B = [hi 64B | lo 64B].
//   A: 128 rows x 128B = 16KB at offset 0
//   B:  96 rows x 128B = 12KB at offset 16384
#define STAGE   28672
#define B_SOFF  16384
#define SMEMSZ  (4 * STAGE)   // 114688  (x2 CTAs = 224KB+res fits 228KB)
#define EPIT    98            // epilogue plane pitch (floats)

// ---------------- kernel: GEMM2 (mma.sync fp16-split) + spline ----------
// CTA: M=128 x N=96 (4 spline groups), K=512 in 16 chunks of 32, occ=2.
// 8 warps as 4(m) x 2(n): warp tile 32 x 48.
// Products: Ah*Bh -> accm; Ah*Bl' + Al'*Bh -> accc (scale 2048, fixed in epi).
__global__ __launch_bounds__(256, 2)
void k_gemm2(const float* __restrict__ b2, const float* __restrict__ x_in,
             const float* __restrict__ ps, float* __restrict__ out_phi) {
    extern __shared__ char sm2[];
    const uint32_t sb = (uint32_t)__cvta_generic_to_shared(sm2);
    const int tid  = threadIdx.x;
    const int wid  = tid >> 5;
    const int lane = tid & 31;
    const int warp_m = wid & 3;
    const int warp_n = wid >> 2;
    const int m0 = blockIdx.x * 128;
    const int n0 = blockIdx.y * 96;

    float accm[12][4], accc[12][4];
#pragma unroll
    for (int t = 0; t < 12; t++)
#pragma unroll
        for (int j = 0; j < 4; j++) { accm[t][j] = 0.f; accc[t][j] = 0.f; }

#define ISSUE(KC)                                                              \
    do {                                                                       \
        const int k0_ = (KC) * 32;                                             \
        const uint32_t st_ = sb + ((KC) & 3) * STAGE;                          \
        _Pragma("unroll")                                                      \
        for (int p_ = 0; p_ < 4; p_++) {          /* A: 1024 16B chunks */     \
            int c_ = tid + p_ * 256;                                           \
            int r_ = c_ >> 3, q_ = c_ & 7;                                     \
            const __half* src_ = ((q_ >> 2) ? g_Al : g_Ah) +                   \
                                 (size_t)(m0 + r_) * HID + k0_ + (q_ & 3) * 8; \
            uint32_t off_ = (uint32_t)(r_ * 128 + q_ * 16);                    \
            CP16(st_ + SWZ128(off_), src_);                                    \
        }                                                                      \
        _Pragma("unroll")                                                      \
        for (int p_ = 0; p_ < 3; p_++) {          /* B: 768 16B chunks */      \
            int c_ = tid + p_ * 256;                                           \
            int r_ = c_ >> 3, q_ = c_ & 7;                                     \
            const __half* src_ = ((q_ >> 2) ? g_Bl : g_Bh) +                   \
                                 (size_t)(n0 + r_) * HID + k0_ + (q_ & 3) * 8; \
            uint32_t off_ = (uint32_t)(r_ * 128 + q_ * 16);                    \
            CP16(st_ + B_SOFF + SWZ128(off_), src_);                           \
        }                                                                      \
        asm volatile("cp.async.commit_group;" ::: "memory");                   \
    } while (0)

    ISSUE(0); ISSUE(1); ISSUE(2);

    for (int kc = 0; kc < 16; kc++) {
        asm volatile("cp.async.wait_group 2;" ::: "memory");
        __syncthreads();
        if (kc < 13) ISSUE(kc + 3);   // overwrites stage (kc-1)&3: safe post-sync

        const uint32_t abase = sb + (kc & 3) * STAGE;
        const uint32_t bbase = abase + B_SOFF;

#pragma unroll
        for (int ks = 0; ks < 2; ks++) {
            uint32_t af[2][2][4];   // [split][mi]
#pragma unroll
            for (int s = 0; s < 2; s++)
#pragma unroll
                for (int mi = 0; mi < 2; mi++) {
                    int row = warp_m * 32 + mi * 16 + (lane & 15);
                    int off = row * 128 + s * 64 + ks * 32 + (lane >> 4) * 16;
                    LDSM4(af[s][mi], abase + SWZ128(off));
                }
#pragma unroll
            for (int s = 0; s < 2; s++) {
                uint32_t bf[6][2];
#pragma unroll
                for (int j = 0; j < 3; j++) {
                    int row = warp_n * 48 + j * 16 + (lane & 7) + ((lane >> 4) & 1) * 8;
                    int off = row * 128 + s * 64 + ks * 32 + ((lane >> 3) & 1) * 16;
                    uint32_t q[4];
                    LDSM4(q, bbase + SWZ128(off));
                    bf[2 * j][0] = q[0]; bf[2 * j][1] = q[1];
                    bf[2 * j + 1][0] = q[2]; bf[2 * j + 1][1] = q[3];
                }
                if (s == 0) {
                    // Ah*Bh -> accm ; Al'*Bh -> accc
#pragma unroll
                    for (int mi = 0; mi < 2; mi++)
#pragma unroll
                        for (int nj = 0; nj < 6; nj++)
                            MMA16816(accm[mi * 6 + nj], af[0][mi], bf[nj]);
#pragma unroll
                    for (int mi = 0; mi < 2; mi++)
#pragma unroll
                        for (int nj = 0; nj < 6; nj++)
                            MMA16816(accc[mi * 6 + nj], af[1][mi], bf[nj]);
                } else {
                    // Ah*Bl' -> accc
#pragma unroll
                    for (int mi = 0; mi < 2; mi++)
#pragma unroll
                        for (int nj = 0; nj < 6; nj++)
                            MMA16816(accc[mi * 6 + nj], af[0][mi], bf[nj]);
                }
            }
        }
    }
    __syncthreads();

    // ---- epilogue: exchange fragments through SMEM, then spline ----
    float* mp = (float*)sm2;               // main plane [128][EPIT]
    float* cpl = (float*)sm2 + 128 * EPIT; // corr plane
#pragma unroll
    for (int mi = 0; mi < 2; mi++)
#pragma unroll
        for (int nj = 0; nj < 6; nj++) {
            int t = mi * 6 + nj;
            int row = warp_m * 32 + mi * 16 + (lane >> 2);
            int col = warp_n * 48 + nj * 8 + (lane & 3) * 2;
            *(float2*)&mp[row * EPIT + col]        = make_float2(accm[t][0], accm[t][1]);
            *(float2*)&mp[(row + 8) * EPIT + col]  = make_float2(accm[t][2], accm[t][3]);
            *(float2*)&cpl[row * EPIT + col]       = make_float2(accc[t][0], accc[t][1]);
            *(float2*)&cpl[(row + 8) * EPIT + col] = make_float2(accc[t][2], accc[t][3]);
        }
    __syncthreads();

#pragma unroll 1
    for (int it = 0; it < 2; it++) {
        int idx = tid + it * 256;          // 512 (b,s) pairs
        int m   = idx >> 2;                // 0..127
        int grp = idx & 3;                 // 0..3
        const int b = m0 + m;
        const int s_glob = blockIdx.y * 4 + grp;
        const int cb = s_glob * 24;
        const int base = m * EPIT + grp * 24;

        // tanh of the 16 h/w raw columns only (d handled lazily below)
        float v[16];
#pragma unroll
        for (int cc = 0; cc < 16; cc++) {
            double mv = (double)mp[base + cc];
            double cv = (double)cpl[base + cc];
            v[cc] = tanhf((float)(mv + cv * LO_INV + (double)b2[cb + cc]));
        }

        float hm = v[0], wm = v[8];
#pragma unroll
        for (int i = 1; i < KNOT; i++) {
            hm = fmaxf(hm, v[i]);
            wm = fmaxf(wm, v[8 + i]);
        }
        float he[KNOT], we[KNOT];
        double hs = 0.0, ws = 0.0;
#pragma unroll
        for (int i = 0; i < KNOT; i++) {
            he[i] = expf(v[i] - hm);      hs += (double)he[i];
            we[i] = expf(v[8 + i] - wm);  ws += (double)we[i];
        }
        double hscale = TWO_PI_D / hs;
        double wscale = TWO_PI_D / ws;
        double h[KNOT], w[KNOT];
#pragma unroll
        for (int i = 0; i < KNOT; i++) {
            h[i] = (double)he[i] * hscale;
            w[i] = (double)we[i] * wscale;
        }

        double x = (double)x_in[(size_t)b * S_OUTD + s_glob];

        int kc2 = 0;
        double cw = 0.0;
#pragma unroll
        for (int i = 0; i < KNOT; i++) {
            cw += w[i];
            kc2 += (cw < x) ? 1 : 0;
        }
        int ki = kc2 < (KNOT - 1) ? kc2 : (KNOT - 1);
        int kn = (ki + 1) & (KNOT - 1);

        double w_k = 0.0, h_k = 0.0, x_km1 = 0.0, phi_km1 = 0.0;
        double pw = 0.0, ph = 0.0;
#pragma unroll
        for (int i = 0; i < KNOT; i++) {
            if (i == ki) {
                w_k = w[i]; h_k = h[i];
                x_km1 = (i == 0) ? -EPS_D : pw;
                phi_km1 = ph;
            }
            pw += w[i];
            ph += h[i];
        }

        // softplus(tanh(.)) only at the 2 needed d indices
        float dr0 = tanhf((float)((double)mp[base + 16 + ki] +
                                  (double)cpl[base + 16 + ki] * LO_INV +
                                  (double)b2[cb + 16 + ki]));
        float dr1 = tanhf((float)((double)mp[base + 16 + kn] +
                                  (double)cpl[base + 16 + kn] * LO_INV +
                                  (double)b2[cb + 16 + kn]));
        double d_k   = (double)log1pf(expf(dr0));
        double d_kp1 = (double)log1pf(expf(dr1));

        double s_k   = h_k / w_k;
        double alpha = (x - x_km1) / w_k;
        double a1m   = alpha * (1.0 - alpha);
        double denom = s_k + (d_kp1 + d_k - 2.0 * s_k) * a1m;
        double phi   = phi_km1 + h_k * (s_k * alpha * alpha + d_k * a1m) / denom;
        phi += (double)ps[0];
        phi = fmod(phi, TWO_PI_D);
        if (phi < 0.0) phi += TWO_PI_D;
        out_phi[(size_t)b * S_OUTD + s_glob] = (float)phi;

        double om   = 1.0 - alpha;
        double grad = s_k * s_k *
                      (d_kp1 * alpha * alpha + 2.0 * s_k * a1m + d_k * om * om) /
                      (denom * denom);
        g_lg[(size_t)b * S_OUTD + s_glob] = logf((float)grad);
    }
#undef ISSUE
}

// ---------------- kernel: deterministic log-density reduction ----------
__global__ void k_ldsum(const float* __restrict__ ld_in,
                        float* __restrict__ out_ld) {
    __shared__ double sh[256];
    int b = blockIdx.x;
    double sm = 0.0;
    for (int i = threadIdx.x; i < S_OUTD; i += 256)
        sm += (double)g_lg[(size_t)b * S_OUTD + i];
    sh[threadIdx.x] = sm;
    __syncthreads();
    for (int o = 128; o > 0; o >>= 1) {
        if (threadIdx.x < o) sh[threadIdx.x] += sh[threadIdx.x + o];
        __syncthreads();
    }
    if (threadIdx.x == 0) out_ld[b] = (float)((double)ld_in[b] - sh[0]);
}

// ---------------- launcher ----------------------------------------------
extern "C" void kernel_launch(void* const* d_in, const int* in_sizes, int n_in,
                              void* d_out, int out_size) {
    const float* x_in      = (const float*)d_in[0];
    const float* x_passive = (const float*)d_in[1];
    const float* ld_in     = (const float*)d_in[2];
    const float* w1        = (const float*)d_in[3];
    const float* b1        = (const float*)d_in[4];
    const float* w2        = (const float*)d_in[5];
    const float* b2        = (const float*)d_in[6];
    const float* ps        = (const float*)d_in[7];
    (void)in_sizes; (void)n_in; (void)out_size;

    float* out_phi = (float*)d_out;
    float* out_ld  = (float*)d_out + (size_t)B_DIM * S_OUTD;

    cudaFuncSetAttribute(k_gemm2, cudaFuncAttributeMaxDynamicSharedMemorySize,
                         SMEMSZ);

    k_zero<<<1, 32>>>();
    k_stats<<<256, 256>>>(x_passive);
    k_finalize<<<1, 32>>>();
    k_xn<<<512, 256>>>(x_passive);
    k_wsplit<<<dim3(NCOL / 32, HID / 64), 256>>>(w2);
    k_gemm1<<<dim3(B_DIM / 64, HID / 64), 256>>>(w1, b1);
    k_gemm2<<<dim3(B_DIM / 128, NCOL / 96), 256, SMEMSZ>>>(b2, x_in, ps, out_phi);
    k_ldsum<<<B_DIM, 256>>>(ld_in, out_ld);
}

// round 7
// speedup vs baseline: 2.0053x; 1.0171x over previous
#include <cuda_runtime.h>
#include <cuda_fp16.h>
#include <cstdint>
#include <math.h>

// Problem constants
#define B_DIM   1024
#define S_IN    4096
#define S_OUTD  4096
#define KNOT    8
#define HID     512
#define NCOL    (S_OUTD * 3 * KNOT)    // 98304
#define NELEM   ((size_t)B_DIM * S_IN) // 4194304
#define TWO_PI_D 6.283185307179586476925286766559
#define EPS_D    1e-6
#define LO_SCALE 2048.0f
#define LO_INV   (1.0 / 2048.0)

// ---------------- device scratch (static, no allocation) ----------------
static __device__ double g_sum;
static __device__ double g_sumsq;
static __device__ float  g_mean;
static __device__ float  g_std;
static __device__ __align__(16) float g_XN[NELEM];                  // 16 MB
static __device__ __align__(16) float g_lg[(size_t)B_DIM * S_OUTD]; // 16 MB
// fp16 2-way splits (lo pre-scaled by 2048) of H and W2^T ([n][k] K-major)
static __device__ __align__(16) __half g_Ah[B_DIM * HID];
static __device__ __align__(16) __half g_Al[B_DIM * HID];
static __device__ __align__(16) __half g_Bh[(size_t)NCOL * HID];
static __device__ __align__(16) __half g_Bl[(size_t)NCOL * HID];

// ---------------- FMA-pipe transcendentals (avoid MUFU) ------------------
// exp(x) for x in ~[-30, 3], rel err ~1e-7. 0 MUFU.
static __device__ __forceinline__ float fexp(float x) {
    float t = x * 1.4426950408889634f;          // log2(e)
    float n = rintf(t);
    float f = fmaf(n, -0.693359375f, x);        // ln2 hi
    f = fmaf(n, 2.12194440e-4f, f);             // ln2 lo
    float p = 1.9841269841e-4f;                 // 1/5040
    p = fmaf(p, f, 1.3888888889e-3f);           // 1/720
    p = fmaf(p, f, 8.3333333333e-3f);           // 1/120
    p = fmaf(p, f, 4.1666666667e-2f);           // 1/24
    p = fmaf(p, f, 1.6666666667e-1f);           // 1/6
    p = fmaf(p, f, 0.5f);
    p = fmaf(p, f, 1.0f);
    p = fmaf(p, f, 1.0f);
    int j = (int)n;
    float s = __int_as_float((j + 127) << 23);
    return p * s;
}

// tanh(x), abs err < 1e-7. 1 MUFU (rcp.approx) + FMA.
static __device__ __forceinline__ float ftanh(float x) {
    float a = fminf(fabsf(x), 9.0f);
    float e = fexp(-2.0f * a);
    float d = 1.0f + e;
    float r;
    asm("rcp.approx.f32 %0, %1;" : "=f"(r) : "f"(d));
    r = r * (2.0f - d * r);                      // Newton -> full fp32
    float tt = (1.0f - e) * r;
    return copysignf(tt, x);
}

// ---------------- small kernels -----------------------------------------
__global__ void k_zero() {
    if (threadIdx.x == 0) { g_sum = 0.0; g_sumsq = 0.0; }
}

__global__ void k_stats(const float* __restrict__ xp) {
    double s = 0.0, s2 = 0.0;
    for (size_t i = (size_t)blockIdx.x * blockDim.x + threadIdx.x; i < NELEM;
         i += (size_t)gridDim.x * blockDim.x) {
        float v = xp[i];
        s  += (double)v;
        s2 += (double)v * (double)v;
    }
    __shared__ double sh[256];
    __shared__ double sh2[256];
    sh[threadIdx.x] = s; sh2[threadIdx.x] = s2;
    __syncthreads();
    for (int o = 128; o > 0; o >>= 1) {
        if (threadIdx.x < o) {
            sh[threadIdx.x]  += sh[threadIdx.x + o];
            sh2[threadIdx.x] += sh2[threadIdx.x + o];
        }
        __syncthreads();
    }
    if (threadIdx.x == 0) {
        atomicAdd(&g_sum,  sh[0]);
        atomicAdd(&g_sumsq, sh2[0]);
    }
}

__global__ void k_finalize() {
    if (threadIdx.x == 0) {
        double n = (double)NELEM;
        double mean = g_sum / n;
        double var  = (g_sumsq - g_sum * g_sum / n) / (n - 1.0);
        g_mean = (float)mean;
        g_std  = (float)sqrt(var);
    }
}

__global__ void k_xn(const float* __restrict__ xp) {
    float mean = g_mean, sd = g_std;
    float inv = 1.0f / sd;
    const float4* src = (const float4*)xp;
    float4* dst = (float4*)g_XN;
    for (size_t i = (size_t)blockIdx.x * blockDim.x + threadIdx.x;
         i < NELEM / 4; i += (size_t)gridDim.x * blockDim.x) {
        float4 v = src[i];
        v.x = (v.x - mean) * inv; v.y = (v.y - mean) * inv;
        v.z = (v.z - mean) * inv; v.w = (v.w - mean) * inv;
        dst[i] = v;
    }
}

// ---------------- kernel: transpose + fp16 2-split of w2 ----------------
__global__ void k_wsplit(const float* __restrict__ w2) {
    __shared__ float t[64][33];
    const int n0 = blockIdx.x * 32, k0 = blockIdx.y * 64;
    const int tid = threadIdx.x;
#pragma unroll
    for (int p = 0; p < 8; p++) {
        int idx = tid + p * 256;
        int kr = idx >> 5, nc = idx & 31;
        t[kr][nc] = w2[(size_t)(k0 + kr) * NCOL + n0 + nc];
    }
    __syncthreads();
#pragma unroll
    for (int p = 0; p < 4; p++) {
        int idx = tid + p * 256;
        int n = idx >> 5, kp = idx & 31;
        float v0 = t[2 * kp][n];
        float v1 = t[2 * kp + 1][n];
        __half h0 = __float2half_rn(v0);
        __half h1 = __float2half_rn(v1);
        __half l0 = __float2half_rn((v0 - __half2float(h0)) * LO_SCALE);
        __half l1 = __float2half_rn((v1 - __half2float(h1)) * LO_SCALE);
        size_t o = ((size_t)(n0 + n) * HID + k0 + 2 * kp) >> 1;
        ((__half2*)g_Bh)[o] = __halves2half2(h0, h1);
        ((__half2*)g_Bl)[o] = __halves2half2(l0, l1);
    }
}

// ---------------- kernel: GEMM1  H = tanh(xn @ w1 + b1), fp16 split -----
__global__ __launch_bounds__(256, 2)
void k_gemm1(const float* __restrict__ w1, const float* __restrict__ b1) {
    __shared__ float As[32 * 68];
    __shared__ __align__(16) float Bs[32 * 64];
    const int tid = threadIdx.x;
    const int m0 = blockIdx.x * 64;
    const int n0 = blockIdx.y * 64;
    const int tx = tid & 15;
    const int ty = tid >> 4;

    float  acc[4][4];
    double accd[4][4];
#pragma unroll
    for (int i = 0; i < 4; i++)
#pragma unroll
        for (int j = 0; j < 4; j++) { acc[i][j] = 0.f; accd[i][j] = 0.0; }

    for (int c = 0; c < S_IN / 32; c++) {
        int k0 = c * 32;
        __syncthreads();
#pragma unroll
        for (int p = 0; p < 2; p++) {
            int idx = tid + p * 256;
            int m  = idx >> 3;
            int kq = idx & 7;
            float4 a = *(const float4*)(g_XN + (size_t)(m0 + m) * S_IN + k0 + kq * 4);
            As[(kq * 4 + 0) * 68 + m] = a.x;
            As[(kq * 4 + 1) * 68 + m] = a.y;
            As[(kq * 4 + 2) * 68 + m] = a.z;
            As[(kq * 4 + 3) * 68 + m] = a.w;
            int kb = idx >> 4;
            int nq = idx & 15;
            *(float4*)(Bs + kb * 64 + nq * 4) =
                *(const float4*)(w1 + (size_t)(k0 + kb) * HID + n0 + nq * 4);
        }
        __syncthreads();
#pragma unroll
        for (int k = 0; k < 32; k++) {
            float4 a = *(const float4*)(As + k * 68 + ty * 4);
            float4 b = *(const float4*)(Bs + k * 64 + tx * 4);
            float av[4] = {a.x, a.y, a.z, a.w};
            float bv[4] = {b.x, b.y, b.z, b.w};
#pragma unroll
            for (int i = 0; i < 4; i++)
#pragma unroll
                for (int j = 0; j < 4; j++) acc[i][j] += av[i] * bv[j];
        }
        if ((c & 1) == 1) {
#pragma unroll
            for (int i = 0; i < 4; i++)
#pragma unroll
                for (int j = 0; j < 4; j++) {
                    accd[i][j] += (double)acc[i][j];
                    acc[i][j] = 0.f;
                }
        }
    }

#pragma unroll
    for (int i = 0; i < 4; i++) {
        int row = m0 + ty * 4 + i;
#pragma unroll
        for (int j = 0; j < 4; j++) {
            int col = n0 + tx * 4 + j;
            float t = tanhf((float)accd[i][j] + b1[col]);
            __half h = __float2half_rn(t);
            float r = t - __half2float(h);
            size_t o = (size_t)row * HID + col;
            g_Ah[o] = h;
            g_Al[o] = __float2half_rn(r * LO_SCALE);
        }
    }
}

// ---------------- mma.sync GEMM2 helpers ---------------------------------
#define SWZ128(x) ((x) ^ (((x) >> 3) & 0x70))

#define LDSM4(r, addr)                                                        \
    asm volatile("ldmatrix.sync.aligned.m8n8.x4.shared.b16 {%0,%1,%2,%3}, [%4];" \
                 : "=r"((r)[0]), "=r"((r)[1]), "=r"((r)[2]), "=r"((r)[3])     \
                 : "r"(addr))

#define MMA16816(d, a, b)                                                     \
    asm volatile("mma.sync.aligned.m16n8k16.row.col.f32.f16.f16.f32 "         \
                 "{%0,%1,%2,%3},{%4,%5,%6,%7},{%8,%9},{%0,%1,%2,%3};"         \
                 : "+f"((d)[0]), "+f"((d)[1]), "+f"((d)[2]), "+f"((d)[3])     \
                 : "r"((a)[0]), "r"((a)[1]), "r"((a)[2]), "r"((a)[3]),        \
                   "r"((b)[0]), "r"((b)[1]))

#define CP16(dst, src)                                                        \
    asm volatile("cp.async.cg.shared.global [%0], [%1], 16;" :: "r"(dst), "l"(src))

// SMEM: 4 stages x 28KB (K-chunk 32). Stage rows are 128B = [hi 64B | lo 64B].
#define STAGE   28672
#define B_SOFF  16384
#define SMEMSZ  (4 * STAGE)   // 114688
#define EPIT    98            // epilogue plane pitch (floats)

// ---------------- kernel: GEMM2 (mma.sync fp16-split) + spline ----------
__global__ __launch_bounds__(256, 2)
void k_gemm2(const float* __restrict__ b2, const float* __restrict__ x_in,
             const float* __restrict__ ps, float* __restrict__ out_phi) {
    extern __shared__ char sm2[];
    const uint32_t sb = (uint32_t)__cvta_generic_to_shared(sm2);
    const int tid  = threadIdx.x;
    const int wid  = tid >> 5;
    const int lane = tid & 31;
    const int warp_m = wid & 3;
    const int warp_n = wid >> 2;
    const int m0 = blockIdx.x * 128;
    const int n0 = blockIdx.y * 96;

    float accm[12][4], accc[12][4];
#pragma unroll
    for (int t = 0; t < 12; t++)
#pragma unroll
        for (int j = 0; j < 4; j++) { accm[t][j] = 0.f; accc[t][j] = 0.f; }

#define ISSUE(KC)                                                              \
    do {                                                                       \
        const int k0_ = (KC) * 32;                                             \
        const uint32_t st_ = sb + ((KC) & 3) * STAGE;                          \
        _Pragma("unroll")                                                      \
        for (int p_ = 0; p_ < 4; p_++) {          /* A: 1024 16B chunks */     \
            int c_ = tid + p_ * 256;                                           \
            int r_ = c_ >> 3, q_ = c_ & 7;                                     \
            const __half* src_ = ((q_ >> 2) ? g_Al : g_Ah) +                   \
                                 (size_t)(m0 + r_) * HID + k0_ + (q_ & 3) * 8; \
            uint32_t off_ = (uint32_t)(r_ * 128 + q_ * 16);                    \
            CP16(st_ + SWZ128(off_), src_);                                    \
        }                                                                      \
        _Pragma("unroll")                                                      \
        for (int p_ = 0; p_ < 3; p_++) {          /* B: 768 16B chunks */      \
            int c_ = tid + p_ * 256;                                           \
            int r_ = c_ >> 3, q_ = c_ & 7;                                     \
            const __half* src_ = ((q_ >> 2) ? g_Bl : g_Bh) +                   \
                                 (size_t)(n0 + r_) * HID + k0_ + (q_ & 3) * 8; \
            uint32_t off_ = (uint32_t)(r_ * 128 + q_ * 16);                    \
            CP16(st_ + B_SOFF + SWZ128(off_), src_);                           \
        }                                                                      \
        asm volatile("cp.async.commit_group;" ::: "memory");                   \
    } while (0)

    ISSUE(0); ISSUE(1); ISSUE(2);

    for (int kc = 0; kc < 16; kc++) {
        asm volatile("cp.async.wait_group 2;" ::: "memory");
        __syncthreads();
        if (kc < 13) ISSUE(kc + 3);

        const uint32_t abase = sb + (kc & 3) * STAGE;
        const uint32_t bbase = abase + B_SOFF;

#pragma unroll
        for (int ks = 0; ks < 2; ks++) {
            uint32_t af[2][2][4];
#pragma unroll
            for (int s = 0; s < 2; s++)
#pragma unroll
                for (int mi = 0; mi < 2; mi++) {
                    int row = warp_m * 32 + mi * 16 + (lane & 15);
                    int off = row * 128 + s * 64 + ks * 32 + (lane >> 4) * 16;
                    LDSM4(af[s][mi], abase + SWZ128(off));
                }
#pragma unroll
            for (int s = 0; s < 2; s++) {
                uint32_t bf[6][2];
#pragma unroll
                for (int j = 0; j < 3; j++) {
                    int row = warp_n * 48 + j * 16 + (lane & 7) + ((lane >> 4) & 1) * 8;
                    int off = row * 128 + s * 64 + ks * 32 + ((lane >> 3) & 1) * 16;
                    uint32_t q[4];
                    LDSM4(q, bbase + SWZ128(off));
                    bf[2 * j][0] = q[0]; bf[2 * j][1] = q[1];
                    bf[2 * j + 1][0] = q[2]; bf[2 * j + 1][1] = q[3];
                }
                if (s == 0) {
#pragma unroll
                    for (int mi = 0; mi < 2; mi++)
#pragma unroll
                        for (int nj = 0; nj < 6; nj++)
                            MMA16816(accm[mi * 6 + nj], af[0][mi], bf[nj]);
#pragma unroll
                    for (int mi = 0; mi < 2; mi++)
#pragma unroll
                        for (int nj = 0; nj < 6; nj++)
                            MMA16816(accc[mi * 6 + nj], af[1][mi], bf[nj]);
                } else {
#pragma unroll
                    for (int mi = 0; mi < 2; mi++)
#pragma unroll
                        for (int nj = 0; nj < 6; nj++)
                            MMA16816(accc[mi * 6 + nj], af[0][mi], bf[nj]);
                }
            }
        }
    }
    __syncthreads();

    // ---- epilogue: exchange fragments through SMEM, then spline ----
    float* mp = (float*)sm2;               // main plane [128][EPIT]
    float* cpl = (float*)sm2 + 128 * EPIT; // corr plane
#pragma unroll
    for (int mi = 0; mi < 2; mi++)
#pragma unroll
        for (int nj = 0; nj < 6; nj++) {
            int t = mi * 6 + nj;
            int row = warp_m * 32 + mi * 16 + (lane >> 2);
            int col = warp_n * 48 + nj * 8 + (lane & 3) * 2;
            *(float2*)&mp[row * EPIT + col]        = make_float2(accm[t][0], accm[t][1]);
            *(float2*)&mp[(row + 8) * EPIT + col]  = make_float2(accm[t][2], accm[t][3]);
            *(float2*)&cpl[row * EPIT + col]       = make_float2(accc[t][0], accc[t][1]);
            *(float2*)&cpl[(row + 8) * EPIT + col] = make_float2(accc[t][2], accc[t][3]);
        }
    __syncthreads();

#pragma unroll 1
    for (int it = 0; it < 2; it++) {
        int idx = tid + it * 256;          // 512 (b,s) pairs
        int m   = idx >> 2;                // 0..127
        int grp = idx & 3;                 // 0..3
        const int b = m0 + m;
        const int s_glob = blockIdx.y * 4 + grp;
        const int cb = s_glob * 24;
        const int base = m * EPIT + grp * 24;

        // tanh of the 16 h/w raw columns (FMA-pipe version)
        float v[16];
#pragma unroll
        for (int cc = 0; cc < 16; cc++) {
            double mv = (double)mp[base + cc];
            double cv = (double)cpl[base + cc];
            v[cc] = ftanh((float)(mv + cv * LO_INV + (double)b2[cb + cc]));
        }

        float hm = v[0], wm = v[8];
#pragma unroll
        for (int i = 1; i < KNOT; i++) {
            hm = fmaxf(hm, v[i]);
            wm = fmaxf(wm, v[8 + i]);
        }
        float he[KNOT], we[KNOT];
        double hs = 0.0, ws = 0.0;
#pragma unroll
        for (int i = 0; i < KNOT; i++) {
            he[i] = fexp(v[i] - hm);      hs += (double)he[i];
            we[i] = fexp(v[8 + i] - wm);  ws += (double)we[i];
        }
        double hscale = TWO_PI_D / hs;
        double wscale = TWO_PI_D / ws;
        double h[KNOT], w[KNOT];
#pragma unroll
        for (int i = 0; i < KNOT; i++) {
            h[i] = (double)he[i] * hscale;
            w[i] = (double)we[i] * wscale;
        }

        double x = (double)x_in[(size_t)b * S_OUTD + s_glob];

        int kc2 = 0;
        double cw = 0.0;
#pragma unroll
        for (int i = 0; i < KNOT; i++) {
            cw += w[i];
            kc2 += (cw < x) ? 1 : 0;
        }
        int ki = kc2 < (KNOT - 1) ? kc2 : (KNOT - 1);
        int kn = (ki + 1) & (KNOT - 1);

        double w_k = 0.0, h_k = 0.0, x_km1 = 0.0, phi_km1 = 0.0;
        double pw = 0.0, ph = 0.0;
#pragma unroll
        for (int i = 0; i < KNOT; i++) {
            if (i == ki) {
                w_k = w[i]; h_k = h[i];
                x_km1 = (i == 0) ? -EPS_D : pw;
                phi_km1 = ph;
            }
            pw += w[i];
            ph += h[i];
        }

        // softplus(tanh(.)) only at the 2 needed d indices
        float dr0 = ftanh((float)((double)mp[base + 16 + ki] +
                                  (double)cpl[base + 16 + ki] * LO_INV +
                                  (double)b2[cb + 16 + ki]));
        float dr1 = ftanh((float)((double)mp[base + 16 + kn] +
                                  (double)cpl[base + 16 + kn] * LO_INV +
                                  (double)b2[cb + 16 + kn]));
        double d_k   = (double)log1pf(fexp(dr0));
        double d_kp1 = (double)log1pf(fexp(dr1));

        double s_k   = h_k / w_k;
        double alpha = (x - x_km1) / w_k;
        double a1m   = alpha * (1.0 - alpha);
        double denom = s_k + (d_kp1 + d_k - 2.0 * s_k) * a1m;
        double phi   = phi_km1 + h_k * (s_k * alpha * alpha + d_k * a1m) / denom;
        phi += (double)ps[0];
        // phi in [0, 2*pi + 1): branchless range reduction replaces fmod
        if (phi >= TWO_PI_D) phi -= TWO_PI_D;
        if (phi >= TWO_PI_D) phi -= TWO_PI_D;
        if (phi < 0.0) phi += TWO_PI_D;
        out_phi[(size_t)b * S_OUTD + s_glob] = (float)phi;

        double om   = 1.0 - alpha;
        double grad = s_k * s_k *
                      (d_kp1 * alpha * alpha + 2.0 * s_k * a1m + d_k * om * om) /
                      (denom * denom);
        g_lg[(size_t)b * S_OUTD + s_glob] = logf((float)grad);
    }
#undef ISSUE
}

// ---------------- kernel: deterministic log-density reduction ----------
__global__ void k_ldsum(const float* __restrict__ ld_in,
                        float* __restrict__ out_ld) {
    __shared__ double sh[256];
    int b = blockIdx.x;
    double sm = 0.0;
    for (int i = threadIdx.x; i < S_OUTD; i += 256)
        sm += (double)g_lg[(size_t)b * S_OUTD + i];
    sh[threadIdx.x] = sm;
    __syncthreads();
    for (int o = 128; o > 0; o >>= 1) {
        if (threadIdx.x < o) sh[threadIdx.x] += sh[threadIdx.x + o];
        __syncthreads();
    }
    if (threadIdx.x == 0) out_ld[b] = (float)((double)ld_in[b] - sh[0]);
}

// ---------------- launcher ----------------------------------------------
extern "C" void kernel_launch(void* const* d_in, const int* in_sizes, int n_in,
                              void* d_out, int out_size) {
    const float* x_in      = (const float*)d_in[0];
    const float* x_passive = (const float*)d_in[1];
    const float* ld_in     = (const float*)d_in[2];
    const float* w1        = (const float*)d_in[3];
    const float* b1        = (const float*)d_in[4];
    const float* w2        = (const float*)d_in[5];
    const float* b2        = (const float*)d_in[6];
    const float* ps        = (const float*)d_in[7];
    (void)in_sizes; (void)n_in; (void)out_size;

    float* out_phi = (float*)d_out;
    float* out_ld  = (float*)d_out + (size_t)B_DIM * S_OUTD;

    cudaFuncSetAttribute(k_gemm2, cudaFuncAttributeMaxDynamicSharedMemorySize,
                         SMEMSZ);

    k_zero<<<1, 32>>>();
    k_stats<<<256, 256>>>(x_passive);
    k_finalize<<<1, 32>>>();
    k_xn<<<512, 256>>>(x_passive);
    k_wsplit<<<dim3(NCOL / 32, HID / 64), 256>>>(w2);
    k_gemm1<<<dim3(B_DIM / 64, HID / 64), 256>>>(w1, b1);
    k_gemm2<<<dim3(B_DIM / 128, NCOL / 96), 256, SMEMSZ>>>(b2, x_in, ps, out_phi);
    k_ldsum<<<B_DIM, 256>>>(ld_in, out_ld);
}

// round 8
// speedup vs baseline: 3.4134x; 1.7022x over previous
#include <cuda_runtime.h>
#include <cuda_fp16.h>
#include <cstdint>
#include <math.h>

// Problem constants
#define B_DIM   1024
#define S_IN    4096
#define S_OUTD  4096
#define KNOT    8
#define HID     512
#define NCOL    (S_OUTD * 3 * KNOT)    // 98304
#define NELEM   ((size_t)B_DIM * S_IN) // 4194304
#define TWO_PI_F 6.28318530717958647692f
#define EPS_F    1e-6f
#define LO_SCALE 2048.0f
#define LO_INVF  (1.0f / 2048.0f)

// ---------------- device scratch (static, no allocation) ----------------
static __device__ double g_sum;
static __device__ double g_sumsq;
static __device__ float  g_mean;
static __device__ float  g_std;
static __device__ __align__(16) float g_XN[NELEM];                  // 16 MB
static __device__ __align__(16) float g_lg[(size_t)B_DIM * S_OUTD]; // 16 MB
// fp16 2-way splits (lo pre-scaled by 2048) of H and W2^T ([n][k] K-major)
static __device__ __align__(16) __half g_Ah[B_DIM * HID];
static __device__ __align__(16) __half g_Al[B_DIM * HID];
static __device__ __align__(16) __half g_Bh[(size_t)NCOL * HID];
static __device__ __align__(16) __half g_Bl[(size_t)NCOL * HID];

// ---------------- FMA-pipe transcendentals (avoid MUFU) ------------------
// exp(x) for x in ~[-30, 3], rel err ~1e-7. 0 MUFU.
static __device__ __forceinline__ float fexp(float x) {
    float t = x * 1.4426950408889634f;          // log2(e)
    float n = rintf(t);
    float f = fmaf(n, -0.693359375f, x);        // ln2 hi
    f = fmaf(n, 2.12194440e-4f, f);             // ln2 lo
    float p = 1.9841269841e-4f;                 // 1/5040
    p = fmaf(p, f, 1.3888888889e-3f);           // 1/720
    p = fmaf(p, f, 8.3333333333e-3f);           // 1/120
    p = fmaf(p, f, 4.1666666667e-2f);           // 1/24
    p = fmaf(p, f, 1.6666666667e-1f);           // 1/6
    p = fmaf(p, f, 0.5f);
    p = fmaf(p, f, 1.0f);
    p = fmaf(p, f, 1.0f);
    int j = (int)n;
    float s = __int_as_float((j + 127) << 23);
    return p * s;
}

// tanh(x), abs err < 1e-7. 1 MUFU (rcp.approx) + FMA.
static __device__ __forceinline__ float ftanh(float x) {
    float a = fminf(fabsf(x), 9.0f);
    float e = fexp(-2.0f * a);
    float d = 1.0f + e;
    float r;
    asm("rcp.approx.f32 %0, %1;" : "=f"(r) : "f"(d));
    r = r * (2.0f - d * r);                      // Newton -> full fp32
    float tt = (1.0f - e) * r;
    return copysignf(tt, x);
}

// ---------------- float-float (TwoSum) helpers, all on FMA pipe ----------
struct ff2 { float hi, lo; };
static __device__ __forceinline__ ff2 ff_renorm(float s, float e) {
    float t = s + e;
    return {t, e - (t - s)};
}
static __device__ __forceinline__ ff2 ff_addf(ff2 a, float b) {
    float s  = a.hi + b;
    float bb = s - a.hi;
    float err = (a.hi - (s - bb)) + (b - bb);
    return ff_renorm(s, err + a.lo);
}

// ---------------- small kernels -----------------------------------------
__global__ void k_zero() {
    if (threadIdx.x == 0) { g_sum = 0.0; g_sumsq = 0.0; }
}

__global__ void k_stats(const float* __restrict__ xp) {
    double s = 0.0, s2 = 0.0;
    for (size_t i = (size_t)blockIdx.x * blockDim.x + threadIdx.x; i < NELEM;
         i += (size_t)gridDim.x * blockDim.x) {
        float v = xp[i];
        s  += (double)v;
        s2 += (double)v * (double)v;
    }
    __shared__ double sh[256];
    __shared__ double sh2[256];
    sh[threadIdx.x] = s; sh2[threadIdx.x] = s2;
    __syncthreads();
    for (int o = 128; o > 0; o >>= 1) {
        if (threadIdx.x < o) {
            sh[threadIdx.x]  += sh[threadIdx.x + o];
            sh2[threadIdx.x] += sh2[threadIdx.x + o];
        }
        __syncthreads();
    }
    if (threadIdx.x == 0) {
        atomicAdd(&g_sum,  sh[0]);
        atomicAdd(&g_sumsq, sh2[0]);
    }
}

__global__ void k_finalize() {
    if (threadIdx.x == 0) {
        double n = (double)NELEM;
        double mean = g_sum / n;
        double var  = (g_sumsq - g_sum * g_sum / n) / (n - 1.0);
        g_mean = (float)mean;
        g_std  = (float)sqrt(var);
    }
}

__global__ void k_xn(const float* __restrict__ xp) {
    float mean = g_mean, sd = g_std;
    float inv = 1.0f / sd;
    const float4* src = (const float4*)xp;
    float4* dst = (float4*)g_XN;
    for (size_t i = (size_t)blockIdx.x * blockDim.x + threadIdx.x;
         i < NELEM / 4; i += (size_t)gridDim.x * blockDim.x) {
        float4 v = src[i];
        v.x = (v.x - mean) * inv; v.y = (v.y - mean) * inv;
        v.z = (v.z - mean) * inv; v.w = (v.w - mean) * inv;
        dst[i] = v;
    }
}

// ---------------- kernel: transpose + fp16 2-split of w2 ----------------
__global__ void k_wsplit(const float* __restrict__ w2) {
    __shared__ float t[64][33];
    const int n0 = blockIdx.x * 32, k0 = blockIdx.y * 64;
    const int tid = threadIdx.x;
#pragma unroll
    for (int p = 0; p < 8; p++) {
        int idx = tid + p * 256;
        int kr = idx >> 5, nc = idx & 31;
        t[kr][nc] = w2[(size_t)(k0 + kr) * NCOL + n0 + nc];
    }
    __syncthreads();
#pragma unroll
    for (int p = 0; p < 4; p++) {
        int idx = tid + p * 256;
        int n = idx >> 5, kp = idx & 31;
        float v0 = t[2 * kp][n];
        float v1 = t[2 * kp + 1][n];
        __half h0 = __float2half_rn(v0);
        __half h1 = __float2half_rn(v1);
        __half l0 = __float2half_rn((v0 - __half2float(h0)) * LO_SCALE);
        __half l1 = __float2half_rn((v1 - __half2float(h1)) * LO_SCALE);
        size_t o = ((size_t)(n0 + n) * HID + k0 + 2 * kp) >> 1;
        ((__half2*)g_Bh)[o] = __halves2half2(h0, h1);
        ((__half2*)g_Bl)[o] = __halves2half2(l0, l1);
    }
}

// ---------------- kernel: GEMM1  H = tanh(xn @ w1 + b1), fp16 split -----
__global__ __launch_bounds__(256, 2)
void k_gemm1(const float* __restrict__ w1, const float* __restrict__ b1) {
    __shared__ float As[32 * 68];
    __shared__ __align__(16) float Bs[32 * 64];
    const int tid = threadIdx.x;
    const int m0 = blockIdx.x * 64;
    const int n0 = blockIdx.y * 64;
    const int tx = tid & 15;
    const int ty = tid >> 4;

    float  acc[4][4];
    double accd[4][4];
#pragma unroll
    for (int i = 0; i < 4; i++)
#pragma unroll
        for (int j = 0; j < 4; j++) { acc[i][j] = 0.f; accd[i][j] = 0.0; }

    for (int c = 0; c < S_IN / 32; c++) {
        int k0 = c * 32;
        __syncthreads();
#pragma unroll
        for (int p = 0; p < 2; p++) {
            int idx = tid + p * 256;
            int m  = idx >> 3;
            int kq = idx & 7;
            float4 a = *(const float4*)(g_XN + (size_t)(m0 + m) * S_IN + k0 + kq * 4);
            As[(kq * 4 + 0) * 68 + m] = a.x;
            As[(kq * 4 + 1) * 68 + m] = a.y;
            As[(kq * 4 + 2) * 68 + m] = a.z;
            As[(kq * 4 + 3) * 68 + m] = a.w;
            int kb = idx >> 4;
            int nq = idx & 15;
            *(float4*)(Bs + kb * 64 + nq * 4) =
                *(const float4*)(w1 + (size_t)(k0 + kb) * HID + n0 + nq * 4);
        }
        __syncthreads();
#pragma unroll
        for (int k = 0; k < 32; k++) {
            float4 a = *(const float4*)(As + k * 68 + ty * 4);
            float4 b = *(const float4*)(Bs + k * 64 + tx * 4);
            float av[4] = {a.x, a.y, a.z, a.w};
            float bv[4] = {b.x, b.y, b.z, b.w};
#pragma unroll
            for (int i = 0; i < 4; i++)
#pragma unroll
                for (int j = 0; j < 4; j++) acc[i][j] += av[i] * bv[j];
        }
        if ((c & 1) == 1) {
#pragma unroll
            for (int i = 0; i < 4; i++)
#pragma unroll
                for (int j = 0; j < 4; j++) {
                    accd[i][j] += (double)acc[i][j];
                    acc[i][j] = 0.f;
                }
        }
    }

#pragma unroll
    for (int i = 0; i < 4; i++) {
        int row = m0 + ty * 4 + i;
#pragma unroll
        for (int j = 0; j < 4; j++) {
            int col = n0 + tx * 4 + j;
            float t = tanhf((float)accd[i][j] + b1[col]);
            __half h = __float2half_rn(t);
            float r = t - __half2float(h);
            size_t o = (size_t)row * HID + col;
            g_Ah[o] = h;
            g_Al[o] = __float2half_rn(r * LO_SCALE);
        }
    }
}

// ---------------- mma.sync GEMM2 helpers ---------------------------------
#define SWZ128(x) ((x) ^ (((x) >> 3) & 0x70))

#define LDSM4(r, addr)                                                        \
    asm volatile("ldmatrix.sync.aligned.m8n8.x4.shared.b16 {%0,%1,%2,%3}, [%4];" \
                 : "=r"((r)[0]), "=r"((r)[1]), "=r"((r)[2]), "=r"((r)[3])     \
                 : "r"(addr))

#define MMA16816(d, a, b)                                                     \
    asm volatile("mma.sync.aligned.m16n8k16.row.col.f32.f16.f16.f32 "         \
                 "{%0,%1,%2,%3},{%4,%5,%6,%7},{%8,%9},{%0,%1,%2,%3};"         \
                 : "+f"((d)[0]), "+f"((d)[1]), "+f"((d)[2]), "+f"((d)[3])     \
                 : "r"((a)[0]), "r"((a)[1]), "r"((a)[2]), "r"((a)[3]),        \
                   "r"((b)[0]), "r"((b)[1]))

#define CP16(dst, src)                                                        \
    asm volatile("cp.async.cg.shared.global [%0], [%1], 16;" :: "r"(dst), "l"(src))

// SMEM: 4 stages x 28KB (K-chunk 32). Stage rows are 128B = [hi 64B | lo 64B].
#define STAGE   28672
#define B_SOFF  16384
#define SMEMSZ  (4 * STAGE)   // 114688
#define EPIT    98            // epilogue plane pitch (floats)

// ---------------- kernel: GEMM2 (mma.sync fp16-split) + spline ----------
__global__ __launch_bounds__(256, 2)
void k_gemm2(const float* __restrict__ b2, const float* __restrict__ x_in,
             const float* __restrict__ ps, float* __restrict__ out_phi) {
    extern __shared__ char sm2[];
    const uint32_t sb = (uint32_t)__cvta_generic_to_shared(sm2);
    const int tid  = threadIdx.x;
    const int wid  = tid >> 5;
    const int lane = tid & 31;
    const int warp_m = wid & 3;
    const int warp_n = wid >> 2;
    const int m0 = blockIdx.x * 128;
    const int n0 = blockIdx.y * 96;

    float accm[12][4], accc[12][4];
#pragma unroll
    for (int t = 0; t < 12; t++)
#pragma unroll
        for (int j = 0; j < 4; j++) { accm[t][j] = 0.f; accc[t][j] = 0.f; }

#define ISSUE(KC)                                                              \
    do {                                                                       \
        const int k0_ = (KC) * 32;                                             \
        const uint32_t st_ = sb + ((KC) & 3) * STAGE;                          \
        _Pragma("unroll")                                                      \
        for (int p_ = 0; p_ < 4; p_++) {          /* A: 1024 16B chunks */     \
            int c_ = tid + p_ * 256;                                           \
            int r_ = c_ >> 3, q_ = c_ & 7;                                     \
            const __half* src_ = ((q_ >> 2) ? g_Al : g_Ah) +                   \
                                 (size_t)(m0 + r_) * HID + k0_ + (q_ & 3) * 8; \
            uint32_t off_ = (uint32_t)(r_ * 128 + q_ * 16);                    \
            CP16(st_ + SWZ128(off_), src_);                                    \
        }                                                                      \
        _Pragma("unroll")                                                      \
        for (int p_ = 0; p_ < 3; p_++) {          /* B: 768 16B chunks */      \
            int c_ = tid + p_ * 256;                                           \
            int r_ = c_ >> 3, q_ = c_ & 7;                                     \
            const __half* src_ = ((q_ >> 2) ? g_Bl : g_Bh) +                   \
                                 (size_t)(n0 + r_) * HID + k0_ + (q_ & 3) * 8; \
            uint32_t off_ = (uint32_t)(r_ * 128 + q_ * 16);                    \
            CP16(st_ + B_SOFF + SWZ128(off_), src_);                           \
        }                                                                      \
        asm volatile("cp.async.commit_group;" ::: "memory");                   \
    } while (0)

    ISSUE(0); ISSUE(1); ISSUE(2);

    for (int kc = 0; kc < 16; kc++) {
        asm volatile("cp.async.wait_group 2;" ::: "memory");
        __syncthreads();
        if (kc < 13) ISSUE(kc + 3);

        const uint32_t abase = sb + (kc & 3) * STAGE;
        const uint32_t bbase = abase + B_SOFF;

#pragma unroll
        for (int ks = 0; ks < 2; ks++) {
            uint32_t af[2][2][4];
#pragma unroll
            for (int s = 0; s < 2; s++)
#pragma unroll
                for (int mi = 0; mi < 2; mi++) {
                    int row = warp_m * 32 + mi * 16 + (lane & 15);
                    int off = row * 128 + s * 64 + ks * 32 + (lane >> 4) * 16;
                    LDSM4(af[s][mi], abase + SWZ128(off));
                }
#pragma unroll
            for (int s = 0; s < 2; s++) {
                uint32_t bf[6][2];
#pragma unroll
                for (int j = 0; j < 3; j++) {
                    int row = warp_n * 48 + j * 16 + (lane & 7) + ((lane >> 4) & 1) * 8;
                    int off = row * 128 + s * 64 + ks * 32 + ((lane >> 3) & 1) * 16;
                    uint32_t q[4];
                    LDSM4(q, bbase + SWZ128(off));
                    bf[2 * j][0] = q[0]; bf[2 * j][1] = q[1];
                    bf[2 * j + 1][0] = q[2]; bf[2 * j + 1][1] = q[3];
                }
                if (s == 0) {
#pragma unroll
                    for (int mi = 0; mi < 2; mi++)
#pragma unroll
                        for (int nj = 0; nj < 6; nj++)
                            MMA16816(accm[mi * 6 + nj], af[0][mi], bf[nj]);
#pragma unroll
                    for (int mi = 0; mi < 2; mi++)
#pragma unroll
                        for (int nj = 0; nj < 6; nj++)
                            MMA16816(accc[mi * 6 + nj], af[1][mi], bf[nj]);
                } else {
#pragma unroll
                    for (int mi = 0; mi < 2; mi++)
#pragma unroll
                        for (int nj = 0; nj < 6; nj++)
                            MMA16816(accc[mi * 6 + nj], af[0][mi], bf[nj]);
                }
            }
        }
    }
    __syncthreads();

    // ---- epilogue: exchange fragments through SMEM, then spline ----
    float* mp = (float*)sm2;               // main plane [128][EPIT]
    float* cpl = (float*)sm2 + 128 * EPIT; // corr plane
#pragma unroll
    for (int mi = 0; mi < 2; mi++)
#pragma unroll
        for (int nj = 0; nj < 6; nj++) {
            int t = mi * 6 + nj;
            int row = warp_m * 32 + mi * 16 + (lane >> 2);
            int col = warp_n * 48 + nj * 8 + (lane & 3) * 2;
            *(float2*)&mp[row * EPIT + col]        = make_float2(accm[t][0], accm[t][1]);
            *(float2*)&mp[(row + 8) * EPIT + col]  = make_float2(accm[t][2], accm[t][3]);
            *(float2*)&cpl[row * EPIT + col]       = make_float2(accc[t][0], accc[t][1]);
            *(float2*)&cpl[(row + 8) * EPIT + col] = make_float2(accc[t][2], accc[t][3]);
        }
    __syncthreads();

    const float psv = ps[0];

#pragma unroll 1
    for (int it = 0; it < 2; it++) {
        int idx = tid + it * 256;          // 512 (b,s) pairs
        int m   = idx >> 2;                // 0..127
        int grp = idx & 3;                 // 0..3
        const int b = m0 + m;
        const int s_glob = blockIdx.y * 4 + grp;
        const int cb = s_glob * 24;
        const int base = m * EPIT + grp * 24;

        // tanh of the 16 h/w raw columns (fp32, FMA pipe)
        float v[16];
#pragma unroll
        for (int cc = 0; cc < 16; cc++) {
            float arg = mp[base + cc] + fmaf(cpl[base + cc], LO_INVF, b2[cb + cc]);
            v[cc] = ftanh(arg);
        }

        float hm = v[0], wm = v[8];
#pragma unroll
        for (int i = 1; i < KNOT; i++) {
            hm = fmaxf(hm, v[i]);
            wm = fmaxf(wm, v[8 + i]);
        }
        float he[KNOT], we[KNOT];
        float hs = 0.f, ws = 0.f;
#pragma unroll
        for (int i = 0; i < KNOT; i++) {
            he[i] = fexp(v[i] - hm);      hs += he[i];
            we[i] = fexp(v[8 + i] - wm);  ws += we[i];
        }
        float hscale = TWO_PI_F / hs;
        float wscale = TWO_PI_F / ws;
        float h[KNOT], w[KNOT];
#pragma unroll
        for (int i = 0; i < KNOT; i++) {
            h[i] = he[i] * hscale;
            w[i] = we[i] * wscale;
        }

        const float x = x_in[(size_t)b * S_OUTD + s_glob];

        // bin index: float-float cumsum of w, compare against x
        int kc2 = 0;
        ff2 cw = {0.f, 0.f};
#pragma unroll
        for (int i = 0; i < KNOT; i++) {
            cw = ff_addf(cw, w[i]);
            kc2 += (((cw.hi - x) + cw.lo) < 0.f) ? 1 : 0;
        }
        int ki = kc2 < (KNOT - 1) ? kc2 : (KNOT - 1);
        int kn = (ki + 1) & (KNOT - 1);

        float w_k = 0.f, h_k = 0.f;
        ff2 x_km1 = {0.f, 0.f}, phi_km1 = {0.f, 0.f};
        ff2 pw = {0.f, 0.f}, ph = {0.f, 0.f};
#pragma unroll
        for (int i = 0; i < KNOT; i++) {
            if (i == ki) {
                w_k = w[i]; h_k = h[i];
                if (i == 0) { x_km1.hi = -EPS_F; x_km1.lo = 0.f; }
                else        { x_km1 = pw; }
                phi_km1 = ph;
            }
            pw = ff_addf(pw, w[i]);
            ph = ff_addf(ph, h[i]);
        }

        // softplus(tanh(.)) only at the 2 needed d indices
        float dr0 = ftanh(mp[base + 16 + ki] +
                          fmaf(cpl[base + 16 + ki], LO_INVF, b2[cb + 16 + ki]));
        float dr1 = ftanh(mp[base + 16 + kn] +
                          fmaf(cpl[base + 16 + kn], LO_INVF, b2[cb + 16 + kn]));
        float d_k   = log1pf(fexp(dr0));
        float d_kp1 = log1pf(fexp(dr1));

        float s_k   = h_k / w_k;
        float alpha = ((x - x_km1.hi) - x_km1.lo) / w_k;
        float a1m   = alpha * (1.f - alpha);
        float denom = s_k + (d_kp1 + d_k - 2.f * s_k) * a1m;
        float frac  = h_k * fmaf(s_k * alpha, alpha, d_k * a1m) / denom;

        // phi accumulation in float-float; wrap in fp32 to mirror reference
        ff2 phif = ff_addf(phi_km1, frac);
        phif = ff_addf(phif, psv);
        float phiv = phif.hi + phif.lo;
        if (phiv >= TWO_PI_F) phiv -= TWO_PI_F;
        if (phiv >= TWO_PI_F) phiv -= TWO_PI_F;
        if (phiv < 0.f) phiv += TWO_PI_F;
        out_phi[(size_t)b * S_OUTD + s_glob] = phiv;

        float om   = 1.f - alpha;
        float grad = s_k * s_k *
                     fmaf(d_kp1 * alpha, alpha, fmaf(2.f * s_k, a1m, d_k * om * om)) /
                     (denom * denom);
        g_lg[(size_t)b * S_OUTD + s_glob] = logf(grad);
    }
#undef ISSUE
}

// ---------------- kernel: deterministic log-density reduction ----------
__global__ void k_ldsum(const float* __restrict__ ld_in,
                        float* __restrict__ out_ld) {
    __shared__ double sh[256];
    int b = blockIdx.x;
    double sm = 0.0;
    for (int i = threadIdx.x; i < S_OUTD; i += 256)
        sm += (double)g_lg[(size_t)b * S_OUTD + i];
    sh[threadIdx.x] = sm;
    __syncthreads();
    for (int o = 128; o > 0; o >>= 1) {
        if (threadIdx.x < o) sh[threadIdx.x] += sh[threadIdx.x + o];
        __syncthreads();
    }
    if (threadIdx.x == 0) out_ld[b] = (float)((double)ld_in[b] - sh[0]);
}

// ---------------- launcher ----------------------------------------------
extern "C" void kernel_launch(void* const* d_in, const int* in_sizes, int n_in,
                              void* d_out, int out_size) {
    const float* x_in      = (const float*)d_in[0];
    const float* x_passive = (const float*)d_in[1];
    const float* ld_in     = (const float*)d_in[2];
    const float* w1        = (const float*)d_in[3];
    const float* b1        = (const float*)d_in[4];
    const float* w2        = (const float*)d_in[5];
    const float* b2        = (const float*)d_in[6];
    const float* ps        = (const float*)d_in[7];
    (void)in_sizes; (void)n_in; (void)out_size;

    float* out_phi = (float*)d_out;
    float* out_ld  = (float*)d_out + (size_t)B_DIM * S_OUTD;

    cudaFuncSetAttribute(k_gemm2, cudaFuncAttributeMaxDynamicSharedMemorySize,
                         SMEMSZ);

    k_zero<<<1, 32>>>();
    k_stats<<<256, 256>>>(x_passive);
    k_finalize<<<1, 32>>>();
    k_xn<<<512, 256>>>(x_passive);
    k_wsplit<<<dim3(NCOL / 32, HID / 64), 256>>>(w2);
    k_gemm1<<<dim3(B_DIM / 64, HID / 64), 256>>>(w1, b1);
    k_gemm2<<<dim3(B_DIM / 128, NCOL / 96), 256, SMEMSZ>>>(b2, x_in, ps, out_phi);
    k_ldsum<<<B_DIM, 256>>>(ld_in, out_ld);
}